// round 8
// baseline (speedup 1.0000x reference)
#include <cuda_runtime.h>
#include <math.h>

// ---------------------------------------------------------------------------
// GPT-2 small forward. fp32 activations; GEMMs use split-tf32 (3xTF32)
// mma.sync on pre-split (hi,lo) float2 operands. 512-thread CTAs, KT=32
// double-buffered tiles, causal-aware attention, 2-term split for the
// (error-terminal) head GEMM.
// ---------------------------------------------------------------------------

namespace {
constexpr int B_  = 4;
constexpr int T_  = 1024;
constexpr int C_  = 768;
constexpr int H_  = 12;
constexpr int HS_ = 64;
constexpr int L_  = 12;
constexpr int V_  = 32000;
constexpr int BT_ = B_ * T_;
constexpr int C4_ = 4 * C_;
constexpr int C3_ = 3 * C_;

constexpr int PG  = 132;                 // smem row pitch in float2
constexpr int KT  = 32;                  // k per tile (main gemm)
constexpr int STG_G = 2 * KT * PG;       // float2 per stage (As + Bs)
constexpr size_t SMEM_G = 2 * STG_G * sizeof(float2);   // 135168 B

constexpr int KTA = 16;                  // k per tile (AV gemm)
constexpr int STG_A = 2 * KTA * PG;
constexpr size_t SMEM_A = 2 * STG_A * sizeof(float2);   // 67584 B
}

// Scratch (no cudaMalloc -> device globals)
__device__ float  g_x   [BT_ * C_];
__device__ float2 g_h2  [BT_ * C_];
__device__ float2 g_qkv2[BT_ * C3_];
__device__ float2 g_o2  [BT_ * C_];
__device__ float2 g_a12 [BT_ * C4_];
__device__ float  g_att [(size_t)B_ * H_ * T_ * T_];
// all-layer pre-split weights
__device__ float2 g_wcat2[(size_t)L_ * C_ * C3_];
__device__ float2 g_wp2  [(size_t)L_ * C_ * C_];
__device__ float2 g_w12  [(size_t)L_ * C_ * C4_];
__device__ float2 g_w22  [(size_t)L_ * C4_ * C_];
__device__ float2 g_wh2  [(size_t)C_ * V_];

// ---------------------------------------------------------------------------
// tf32 helpers
// ---------------------------------------------------------------------------
__device__ __forceinline__ float2 tf32_split2(float x) {
    unsigned h;
    asm("cvt.rna.tf32.f32 %0, %1;" : "=r"(h) : "f"(x));
    float hf = __uint_as_float(h);
    float l  = x - hf;                       // exact in fp32
    unsigned lu;
    asm("cvt.rna.tf32.f32 %0, %1;" : "=r"(lu) : "f"(l));
    return make_float2(hf, __uint_as_float(lu));
}

__device__ __forceinline__ void mma_tf32(float* d, const unsigned* a, const unsigned* b) {
    asm volatile(
        "mma.sync.aligned.m16n8k8.row.col.f32.tf32.tf32.f32 "
        "{%0,%1,%2,%3}, {%4,%5,%6,%7}, {%8,%9}, {%0,%1,%2,%3};"
        : "+f"(d[0]), "+f"(d[1]), "+f"(d[2]), "+f"(d[3])
        : "r"(a[0]), "r"(a[1]), "r"(a[2]), "r"(a[3]),
          "r"(b[0]), "r"(b[1]));
}

// ---------------------------------------------------------------------------
// Main GEMM: 512 threads, tile 128x128x32, 16 warps (4x4), warp tile 32x32.
// A2,B2 pre-split float2. C = alpha*A@B (+bias)(+gelu)(+resid); out plain or
// split. causalSkip skips blocks with bx > by. threeTerm: 3-term split-tf32
// (fp32-accurate) vs 2-term (B tf32-rounded; ~1.5e-4, for the head GEMM).
// M%128==0, K%32==0 except scores K=64 (%32 ok); N guarded (all N%64==0).
// ---------------------------------------------------------------------------
__global__ void __launch_bounds__(512)
gemm512(const float2* __restrict__ A, const float2* __restrict__ Bp,
        float* __restrict__ Cp,
        int M, int N, int K, int lda, int ldb, int ldc,
        long long sAb, long long sAh, long long sBb, long long sBh,
        long long sCb, long long sCh, int nH,
        const float* __restrict__ bias, const float* __restrict__ resid,
        float alpha, int doGelu, int transB, int outSplit, int causalSkip,
        int threeTerm)
{
    if (causalSkip && blockIdx.x > blockIdx.y) return;
    extern __shared__ float2 smbuf[];

    int bz = blockIdx.z;
    int bb = bz / nH, hh = bz - bb * nH;
    A  += bb * sAb + hh * sAh;
    Bp += bb * sBb + hh * sBh;
    const float* Rp = resid ? (resid + bb * sCb + hh * sCh) : (const float*)0;

    int m0   = blockIdx.y << 7;
    int n0   = blockIdx.x << 7;
    int tid  = threadIdx.x;
    int lane = tid & 31;
    int wid  = tid >> 5;
    int wm   = (wid & 3) << 5;      // 0,32,64,96
    int wn   = (wid >> 2) << 5;     // 0,32,64,96

    float acc[2][4][4];
    #pragma unroll
    for (int a = 0; a < 2; a++)
        #pragma unroll
        for (int b = 0; b < 4; b++)
            #pragma unroll
            for (int j = 0; j < 4; j++) acc[a][b][j] = 0.f;

    // loader patterns (float2 element units)
    const int la_m = tid >> 2;              // 0..127
    const int la_k = (tid & 3) << 3;        // 0,8,16,24 (8 consecutive k)
    const int lb_k = tid >> 4;              // 0..31
    const int lb_n = (tid & 15) << 3;       // 0..120 (8 consecutive n)

    float4 ra[4], rb[4];
    const int nk = K >> 5;

    auto LOAD = [&](int k0) {
        {
            const float4* p = (const float4*)(A + (size_t)(m0 + la_m) * lda + (k0 + la_k));
            ra[0] = p[0]; ra[1] = p[1]; ra[2] = p[2]; ra[3] = p[3];
        }
        if (transB) {
            if (n0 + la_m < N) {
                const float4* p = (const float4*)(Bp + (size_t)(n0 + la_m) * ldb + (k0 + la_k));
                rb[0] = p[0]; rb[1] = p[1]; rb[2] = p[2]; rb[3] = p[3];
            } else {
                rb[0] = rb[1] = rb[2] = rb[3] = make_float4(0.f,0.f,0.f,0.f);
            }
        } else {
            if (n0 + lb_n < N) {
                const float4* p = (const float4*)(Bp + (size_t)(k0 + lb_k) * ldb + (n0 + lb_n));
                rb[0] = p[0]; rb[1] = p[1]; rb[2] = p[2]; rb[3] = p[3];
            } else {
                rb[0] = rb[1] = rb[2] = rb[3] = make_float4(0.f,0.f,0.f,0.f);
            }
        }
    };

    auto STORE = [&](int s) {
        float2* As = smbuf + s * STG_G;
        float2* Bs = As + KT * PG;
        #pragma unroll
        for (int j = 0; j < 4; j++) {
            As[(la_k + 2*j + 0) * PG + la_m] = make_float2(ra[j].x, ra[j].y);
            As[(la_k + 2*j + 1) * PG + la_m] = make_float2(ra[j].z, ra[j].w);
        }
        if (transB) {
            #pragma unroll
            for (int j = 0; j < 4; j++) {
                Bs[(la_k + 2*j + 0) * PG + la_m] = make_float2(rb[j].x, rb[j].y);
                Bs[(la_k + 2*j + 1) * PG + la_m] = make_float2(rb[j].z, rb[j].w);
            }
        } else {
            #pragma unroll
            for (int j = 0; j < 4; j++)
                *(float4*)&Bs[lb_k * PG + lb_n + 2*j] = rb[j];
        }
    };

    LOAD(0);
    STORE(0);
    __syncthreads();

    for (int t = 0; t < nk; t++) {
        if (t + 1 < nk) LOAD((t + 1) << 5);

        const float2* As = smbuf + (t & 1) * STG_G;
        const float2* Bs = As + KT * PG;

        #pragma unroll
        for (int kk = 0; kk < KT; kk += 8) {
            int ck = kk + (lane & 3);
            int qd = lane >> 2;
            float2 af[2][4];
            #pragma unroll
            for (int mt = 0; mt < 2; mt++) {
                int r = wm + (mt << 4) + qd;
                af[mt][0] = As[ck * PG + r];
                af[mt][1] = As[ck * PG + r + 8];
                af[mt][2] = As[(ck + 4) * PG + r];
                af[mt][3] = As[(ck + 4) * PG + r + 8];
            }
            float2 bf[4][2];
            #pragma unroll
            for (int nt = 0; nt < 4; nt++) {
                int cn = wn + (nt << 3) + qd;
                bf[nt][0] = Bs[ck * PG + cn];
                bf[nt][1] = Bs[(ck + 4) * PG + cn];
            }
            #pragma unroll
            for (int mt = 0; mt < 2; mt++) {
                unsigned ah[4], al[4];
                #pragma unroll
                for (int i2 = 0; i2 < 4; i2++) {
                    ah[i2] = __float_as_uint(af[mt][i2].x);
                    al[i2] = __float_as_uint(af[mt][i2].y);
                }
                #pragma unroll
                for (int nt = 0; nt < 4; nt++) {
                    unsigned bh[2] = {__float_as_uint(bf[nt][0].x), __float_as_uint(bf[nt][1].x)};
                    unsigned bl[2] = {__float_as_uint(bf[nt][0].y), __float_as_uint(bf[nt][1].y)};
                    mma_tf32(acc[mt][nt], ah, bh);
                    mma_tf32(acc[mt][nt], ah, bl);
                    if (threeTerm) mma_tf32(acc[mt][nt], al, bh);
                }
            }
        }

        if (t + 1 < nk) STORE((t + 1) & 1);
        __syncthreads();
    }

    // ---- epilogue ----
    float*  Co = Cp + bb * sCb + hh * sCh;
    float2* C2 = (float2*)Cp + bb * sCb + hh * sCh;
    #pragma unroll
    for (int mt = 0; mt < 2; mt++) {
        #pragma unroll
        for (int nt = 0; nt < 4; nt++) {
            int row = m0 + wm + (mt << 4) + (lane >> 2);
            int col = n0 + wn + (nt << 3) + ((lane & 3) << 1);
            #pragma unroll
            for (int j = 0; j < 4; j++) {
                int r = row + ((j & 2) ? 8 : 0);
                int c = col + (j & 1);
                if (c < N) {
                    float v2 = acc[mt][nt][j] * alpha;
                    if (bias) v2 += bias[c];
                    if (doGelu) v2 = 0.5f * v2 * (1.f + erff(v2 * 0.70710678118654752f));
                    if (Rp) v2 += Rp[(size_t)r * ldc + c];
                    if (outSplit) C2[(size_t)r * ldc + c] = tf32_split2(v2);
                    else          Co[(size_t)r * ldc + c] = v2;
                }
            }
        }
    }
}

// ---------------------------------------------------------------------------
// AV GEMM: o[b,h] = P[1024,1024] @ V[1024,64]. 256 threads, warp tile 16x64
// (8 warps x 1). A is PLAIN float (att), split during smem store (each P tile
// loaded exactly once). K clamped causally per block row. Output split.
// ---------------------------------------------------------------------------
__global__ void __launch_bounds__(256)
gemm_av(const float* __restrict__ A, const float2* __restrict__ Bp,
        float2* __restrict__ Cp,
        int K, int lda, int ldb, int ldc,
        long long sAb, long long sAh, long long sBb, long long sBh,
        long long sCb, long long sCh, int nH)
{
    extern __shared__ float2 smbuf[];
    constexpr int N = HS_;

    int bz = blockIdx.z;
    int bb = bz / nH, hh = bz - bb * nH;
    A  += bb * sAb + hh * sAh;
    Bp += bb * sBb + hh * sBh;
    float2* C2 = Cp + bb * sCb + hh * sCh;

    int m0   = blockIdx.y << 7;
    int tid  = threadIdx.x;
    int lane = tid & 31;
    int wid  = tid >> 5;
    int wm   = wid << 4;

    int K_eff = m0 + 128;           // causal clamp
    if (K_eff > K) K_eff = K;
    const int nk = K_eff >> 4;

    float acc[8][4];
    #pragma unroll
    for (int b = 0; b < 8; b++)
        #pragma unroll
        for (int j = 0; j < 4; j++) acc[b][j] = 0.f;

    const int la_m = tid >> 2;
    const int la_k = (tid & 3) << 2;
    const int lb_k = tid >> 5;
    const int lb_n = (tid & 31) << 2;

    float4 ra[2], rb[2][2];

    auto LOAD = [&](int k0) {
        #pragma unroll
        for (int j = 0; j < 2; j++) {
            int m = la_m + (j << 6);
            ra[j] = *(const float4*)(A + (size_t)(m0 + m) * lda + (k0 + la_k));
        }
        #pragma unroll
        for (int j = 0; j < 2; j++) {
            int kk = lb_k + (j << 3);
            if (lb_n < N) {
                const float4* p = (const float4*)(Bp + (size_t)(k0 + kk) * ldb + lb_n);
                rb[j][0] = p[0]; rb[j][1] = p[1];
            } else {
                rb[j][0] = make_float4(0.f,0.f,0.f,0.f);
                rb[j][1] = make_float4(0.f,0.f,0.f,0.f);
            }
        }
    };

    auto STORE = [&](int s) {
        float2* As = smbuf + s * STG_A;
        float2* Bs = As + KTA * PG;
        #pragma unroll
        for (int j = 0; j < 2; j++) {
            int m = la_m + (j << 6);
            float v[4] = {ra[j].x, ra[j].y, ra[j].z, ra[j].w};
            #pragma unroll
            for (int q = 0; q < 4; q++)
                As[(la_k + q) * PG + m] = tf32_split2(v[q]);
        }
        #pragma unroll
        for (int j = 0; j < 2; j++) {
            int kk = lb_k + (j << 3);
            *(float4*)&Bs[kk * PG + lb_n]     = rb[j][0];
            *(float4*)&Bs[kk * PG + lb_n + 2] = rb[j][1];
        }
    };

    LOAD(0);
    STORE(0);
    __syncthreads();

    for (int t = 0; t < nk; t++) {
        if (t + 1 < nk) LOAD((t + 1) << 4);

        const float2* As = smbuf + (t & 1) * STG_A;
        const float2* Bs = As + KTA * PG;

        #pragma unroll
        for (int kk = 0; kk < KTA; kk += 8) {
            int ck = kk + (lane & 3);
            int qd = lane >> 2;
            float2 af[4];
            {
                int r = wm + qd;
                af[0] = As[ck * PG + r];
                af[1] = As[ck * PG + r + 8];
                af[2] = As[(ck + 4) * PG + r];
                af[3] = As[(ck + 4) * PG + r + 8];
            }
            unsigned ah[4], al[4];
            #pragma unroll
            for (int i2 = 0; i2 < 4; i2++) {
                ah[i2] = __float_as_uint(af[i2].x);
                al[i2] = __float_as_uint(af[i2].y);
            }
            #pragma unroll
            for (int nt = 0; nt < 8; nt++) {
                int cn = (nt << 3) + qd;
                float2 b0 = Bs[ck * PG + cn];
                float2 b1 = Bs[(ck + 4) * PG + cn];
                unsigned bh[2] = {__float_as_uint(b0.x), __float_as_uint(b1.x)};
                unsigned bl[2] = {__float_as_uint(b0.y), __float_as_uint(b1.y)};
                mma_tf32(acc[nt], ah, bh);
                mma_tf32(acc[nt], ah, bl);
                mma_tf32(acc[nt], al, bh);
            }
        }

        if (t + 1 < nk) STORE((t + 1) & 1);
        __syncthreads();
    }

    #pragma unroll
    for (int nt = 0; nt < 8; nt++) {
        int row = m0 + wm + (lane >> 2);
        int col = (nt << 3) + ((lane & 3) << 1);
        #pragma unroll
        for (int j = 0; j < 4; j++) {
            int r = row + ((j & 2) ? 8 : 0);
            int c = col + (j & 1);
            if (c < N)
                C2[(size_t)r * ldc + c] = tf32_split2(acc[nt][j]);
        }
    }
}

// ---------------------------------------------------------------------------
// Elementwise split (batched over all layers)
// ---------------------------------------------------------------------------
__global__ void split_k(const float* __restrict__ src, float2* __restrict__ dst, int n4)
{
    int i = blockIdx.x * 256 + threadIdx.x;
    if (i < n4) {
        float4 v = ((const float4*)src)[i];
        dst[4 * i + 0] = tf32_split2(v.x);
        dst[4 * i + 1] = tf32_split2(v.y);
        dst[4 * i + 2] = tf32_split2(v.z);
        dst[4 * i + 3] = tf32_split2(v.w);
    }
}

// Pack Wq/Wk/Wv [L,C,C] into split Wcat2 [L][C][3C], all layers at once.
__global__ void pack_qkv_split(const float* __restrict__ Wq, const float* __restrict__ Wk,
                               const float* __restrict__ Wv, float2* __restrict__ Wcat)
{
    int i = blockIdx.x * 256 + threadIdx.x;
    if (i < L_ * C_ * C_) {
        int l = i / (C_ * C_);
        int r = i - l * (C_ * C_);
        int k = r / C_, j = r - k * C_;
        float2* W = Wcat + (size_t)l * C_ * C3_;
        W[(size_t)k * C3_ + j]          = tf32_split2(Wq[i]);
        W[(size_t)k * C3_ + C_ + j]     = tf32_split2(Wk[i]);
        W[(size_t)k * C3_ + 2 * C_ + j] = tf32_split2(Wv[i]);
    }
}

// ---------------------------------------------------------------------------
// LayerNorm (biased variance, eps=1e-5) -> split float2 output
// ---------------------------------------------------------------------------
__global__ void layernorm_split(const float* __restrict__ x, const float* __restrict__ g,
                                const float* __restrict__ b, float2* __restrict__ y)
{
    int row = blockIdx.x;
    const float* xr = x + (size_t)row * C_;
    float2* yr      = y + (size_t)row * C_;
    int tid = threadIdx.x;
    float s = 0.f, s2 = 0.f;
    for (int c = tid; c < C_; c += 256) { float v = xr[c]; s += v; s2 += v * v; }
    __shared__ float shs[8], shs2[8];
    #pragma unroll
    for (int o = 16; o; o >>= 1) {
        s  += __shfl_xor_sync(0xffffffffu, s,  o);
        s2 += __shfl_xor_sync(0xffffffffu, s2, o);
    }
    if ((tid & 31) == 0) { shs[tid >> 5] = s; shs2[tid >> 5] = s2; }
    __syncthreads();
    float ts = 0.f, ts2 = 0.f;
    #pragma unroll
    for (int i = 0; i < 8; i++) { ts += shs[i]; ts2 += shs2[i]; }
    float mean = ts * (1.f / C_);
    float var  = ts2 * (1.f / C_) - mean * mean;
    float rstd = rsqrtf(var + 1e-5f);
    for (int c = tid; c < C_; c += 256)
        yr[c] = tf32_split2((xr[c] - mean) * rstd * g[c] + b[c]);
}

// ---------------------------------------------------------------------------
// Causal softmax in place; reads valid prefix, writes to next 128 boundary.
// ---------------------------------------------------------------------------
__global__ void softmax_causal(float* __restrict__ att)
{
    int row = blockIdx.x;             // b*H*T + h*T + q
    int q   = row & (T_ - 1);
    float* a = att + (size_t)row * T_;
    int len  = q + 1;
    int wlim = ((q >> 7) + 1) << 7;
    int tid  = threadIdx.x;
    __shared__ float sh[8];

    float r[4];
    #pragma unroll
    for (int i = 0; i < 4; i++) {
        int c = tid + (i << 8);
        r[i] = (c < len) ? a[c] : -3.0e38f;
    }
    float mx = fmaxf(fmaxf(r[0], r[1]), fmaxf(r[2], r[3]));
    #pragma unroll
    for (int o = 16; o; o >>= 1) mx = fmaxf(mx, __shfl_xor_sync(0xffffffffu, mx, o));
    if ((tid & 31) == 0) sh[tid >> 5] = mx;
    __syncthreads();
    mx = sh[0];
    #pragma unroll
    for (int i = 1; i < 8; i++) mx = fmaxf(mx, sh[i]);
    __syncthreads();

    float s = 0.f;
    #pragma unroll
    for (int i = 0; i < 4; i++) {
        int c = tid + (i << 8);
        r[i] = (c < len) ? expf(r[i] - mx) : 0.f;
        s += r[i];
    }
    #pragma unroll
    for (int o = 16; o; o >>= 1) s += __shfl_xor_sync(0xffffffffu, s, o);
    if ((tid & 31) == 0) sh[tid >> 5] = s;
    __syncthreads();
    float tot = 0.f;
    #pragma unroll
    for (int i = 0; i < 8; i++) tot += sh[i];
    float inv = 1.f / tot;

    #pragma unroll
    for (int i = 0; i < 4; i++) {
        int c = tid + (i << 8);
        if (c < wlim) a[c] = r[i] * inv;
    }
}

// ---------------------------------------------------------------------------
// Embedding
// ---------------------------------------------------------------------------
__global__ void embed_k(const int* __restrict__ idx, const float* __restrict__ tok,
                        const float* __restrict__ pos, float* __restrict__ x)
{
    int r = blockIdx.x;
    int t = r & (T_ - 1);
    int token = idx[r];
    const float* te = tok + (size_t)token * C_;
    const float* pe = pos + (size_t)t * C_;
    float* xr = x + (size_t)r * C_;
    for (int c = threadIdx.x; c < C_; c += 256) xr[c] = te[c] + pe[c];
}

// ---------------------------------------------------------------------------
// Launch
// ---------------------------------------------------------------------------
extern "C" void kernel_launch(void* const* d_in, const int* in_sizes, int n_in,
                              void* d_out, int out_size)
{
    (void)in_sizes; (void)n_in; (void)out_size;
    const int*   idx = (const int*)d_in[0];
    const float* tok = (const float*)d_in[1];
    const float* pos = (const float*)d_in[2];
    const float* Wq  = (const float*)d_in[3];
    const float* Wk  = (const float*)d_in[4];
    const float* Wv  = (const float*)d_in[5];
    const float* Wp  = (const float*)d_in[6];
    const float* bp  = (const float*)d_in[7];
    const float* g1  = (const float*)d_in[8];
    const float* be1 = (const float*)d_in[9];
    const float* g2  = (const float*)d_in[10];
    const float* be2 = (const float*)d_in[11];
    const float* W1  = (const float*)d_in[12];
    const float* bb1 = (const float*)d_in[13];
    const float* W2  = (const float*)d_in[14];
    const float* bb2 = (const float*)d_in[15];
    const float* gf  = (const float*)d_in[16];
    const float* bf  = (const float*)d_in[17];
    const float* Wh  = (const float*)d_in[18];
    const float* bhd = (const float*)d_in[19];
    float* out = (float*)d_out;

    float  *x, *att;
    float2 *h2, *qkv2, *o2, *a12, *wcat2, *wp2, *w12, *w22, *wh2;
    cudaGetSymbolAddress((void**)&x,     g_x);
    cudaGetSymbolAddress((void**)&h2,    g_h2);
    cudaGetSymbolAddress((void**)&qkv2,  g_qkv2);
    cudaGetSymbolAddress((void**)&o2,    g_o2);
    cudaGetSymbolAddress((void**)&a12,   g_a12);
    cudaGetSymbolAddress((void**)&att,   g_att);
    cudaGetSymbolAddress((void**)&wcat2, g_wcat2);
    cudaGetSymbolAddress((void**)&wp2,   g_wp2);
    cudaGetSymbolAddress((void**)&w12,   g_w12);
    cudaGetSymbolAddress((void**)&w22,   g_w22);
    cudaGetSymbolAddress((void**)&wh2,   g_wh2);

    cudaFuncSetAttribute((const void*)gemm512,
                         cudaFuncAttributeMaxDynamicSharedMemorySize, (int)SMEM_G);
    cudaFuncSetAttribute((const void*)gemm_av,
                         cudaFuncAttributeMaxDynamicSharedMemorySize, (int)SMEM_A);

    const float att_scale = 0.03608439182435161f;  // 768^-0.5 (reference uses full C)
    const float* NOF = (const float*)0;

    embed_k<<<BT_, 256>>>(idx, tok, pos, x);

    // --- pre-split all weights (batched over layers) ---
    pack_qkv_split<<<(L_ * C_ * C_ + 255) / 256, 256>>>(Wq, Wk, Wv, wcat2);
    split_k<<<(L_ * C_ * C_  / 4 + 255) / 256, 256>>>(Wp, wp2, L_ * C_ * C_  / 4);
    split_k<<<(L_ * C_ * C4_ / 4 + 255) / 256, 256>>>(W1, w12, L_ * C_ * C4_ / 4);
    split_k<<<(L_ * C4_ * C_ / 4 + 255) / 256, 256>>>(W2, w22, L_ * C4_ * C_ / 4);
    split_k<<<(C_ * V_ / 4 + 255) / 256, 256>>>(Wh, wh2, C_ * V_ / 4);

    dim3 gqkv(C3_ / 128, BT_ / 128, 1);
    dim3 gcc (C_  / 128, BT_ / 128, 1);
    dim3 gsc (T_  / 128, T_  / 128, B_ * H_);
    dim3 gav (1,         T_  / 128, B_ * H_);
    dim3 gf1 (C4_ / 128, BT_ / 128, 1);

    for (int l = 0; l < L_; l++) {
        layernorm_split<<<BT_, 256>>>(x, g1 + l * C_, be1 + l * C_, h2);

        // qkv = h @ Wcat -> split [BT, 3C]
        gemm512<<<gqkv, 512, SMEM_G>>>(h2, wcat2 + (size_t)l * C_ * C3_, (float*)qkv2,
                BT_, C3_, C_, C_, C3_, C3_,
                0, 0, 0, 0, 0, 0, 1, NOF, NOF, 1.f, 0, 0, 1, 0, 1);

        // scores: Q @ K^T per (b,h) -> plain att, upper blocks skipped
        gemm512<<<gsc, 512, SMEM_G>>>(qkv2, qkv2 + C_, att,
                T_, T_, HS_, C3_, C3_, T_,
                (long long)T_ * C3_, (long long)HS_,
                (long long)T_ * C3_, (long long)HS_,
                (long long)H_ * T_ * T_, (long long)T_ * T_, H_,
                NOF, NOF, att_scale, 0, 1, 0, 1, 1);

        softmax_causal<<<B_ * H_ * T_, 256>>>(att);

        // AV: P @ V -> split o (causally clamped K)
        gemm_av<<<gav, 256, SMEM_A>>>(att, qkv2 + 2 * C_, o2,
                T_, T_, C3_, C_,
                (long long)H_ * T_ * T_, (long long)T_ * T_,
                (long long)T_ * C3_, (long long)HS_,
                (long long)T_ * C_, (long long)HS_, H_);

        // x = x + o @ Wproj + bproj (plain out)
        gemm512<<<gcc, 512, SMEM_G>>>(o2, wp2 + (size_t)l * C_ * C_, x,
                BT_, C_, C_, C_, C_, C_,
                0, 0, 0, 0, 0, 0, 1, bp + l * C_, x, 1.f, 0, 0, 0, 0, 1);

        layernorm_split<<<BT_, 256>>>(x, g2 + l * C_, be2 + l * C_, h2);

        // a1 = gelu(h @ W1 + b1) -> split
        gemm512<<<gf1, 512, SMEM_G>>>(h2, w12 + (size_t)l * C_ * C4_, (float*)a12,
                BT_, C4_, C_, C_, C4_, C4_,
                0, 0, 0, 0, 0, 0, 1, bb1 + l * C4_, NOF, 1.f, 1, 0, 1, 0, 1);

        // x = x + a1 @ W2 + b2 (plain out)
        gemm512<<<gcc, 512, SMEM_G>>>(a12, w22 + (size_t)l * C4_ * C_, x,
                BT_, C_, C4_, C4_, C_, C_,
                0, 0, 0, 0, 0, 0, 1, bb2 + l * C_, x, 1.f, 0, 0, 0, 0, 1);
    }

    layernorm_split<<<BT_, 256>>>(x, gf, bf, h2);

    // head: 2-term split (error-terminal GEMM; ~1.5e-4 rel, 33% fewer MMAs)
    dim3 ghd(V_ / 128, BT_ / 128, 1);
    gemm512<<<ghd, 512, SMEM_G>>>(h2, wh2, out,
            BT_, V_, C_, C_, V_, V_,
            0, 0, 0, 0, 0, 0, 1, bhd, NOF, 1.f, 0, 0, 0, 0, 0);
}

// round 9
// speedup vs baseline: 1.1355x; 1.1355x over previous
#include <cuda_runtime.h>
#include <math.h>

// ---------------------------------------------------------------------------
// GPT-2 small forward. fp32 activations; GEMMs use split-tf32 (3xTF32)
// mma.sync on pre-split (hi,lo) float2 operands. 512-thread CTAs, KT=16
// double-buffered tiles (R7 config), causal-aware attention, 2-term split
// for the error-terminal head GEMM only.
// ---------------------------------------------------------------------------

namespace {
constexpr int B_  = 4;
constexpr int T_  = 1024;
constexpr int C_  = 768;
constexpr int H_  = 12;
constexpr int HS_ = 64;
constexpr int L_  = 12;
constexpr int V_  = 32000;
constexpr int BT_ = B_ * T_;
constexpr int C4_ = 4 * C_;
constexpr int C3_ = 3 * C_;

constexpr int KT = 16;              // k per tile
constexpr int P  = 132;             // smem row pitch in float2
constexpr int STG = 2 * KT * P;     // float2 per stage (As + Bs)
constexpr size_t SMEM_BYTES = 2 * STG * sizeof(float2);   // 67584 B
}

// Scratch (no cudaMalloc -> device globals)
__device__ float  g_x   [BT_ * C_];
__device__ float2 g_h2  [BT_ * C_];
__device__ float2 g_qkv2[BT_ * C3_];
__device__ float2 g_o2  [BT_ * C_];
__device__ float2 g_a12 [BT_ * C4_];
__device__ float  g_att [(size_t)B_ * H_ * T_ * T_];
// all-layer pre-split weights
__device__ float2 g_wcat2[(size_t)L_ * C_ * C3_];
__device__ float2 g_wp2  [(size_t)L_ * C_ * C_];
__device__ float2 g_w12  [(size_t)L_ * C_ * C4_];
__device__ float2 g_w22  [(size_t)L_ * C4_ * C_];
__device__ float2 g_wh2  [(size_t)C_ * V_];

// ---------------------------------------------------------------------------
// tf32 helpers
// ---------------------------------------------------------------------------
__device__ __forceinline__ float2 tf32_split2(float x) {
    unsigned h;
    asm("cvt.rna.tf32.f32 %0, %1;" : "=r"(h) : "f"(x));
    float hf = __uint_as_float(h);
    float l  = x - hf;                       // exact in fp32
    unsigned lu;
    asm("cvt.rna.tf32.f32 %0, %1;" : "=r"(lu) : "f"(l));
    return make_float2(hf, __uint_as_float(lu));
}

__device__ __forceinline__ void mma_tf32(float* d, const unsigned* a, const unsigned* b) {
    asm volatile(
        "mma.sync.aligned.m16n8k8.row.col.f32.tf32.tf32.f32 "
        "{%0,%1,%2,%3}, {%4,%5,%6,%7}, {%8,%9}, {%0,%1,%2,%3};"
        : "+f"(d[0]), "+f"(d[1]), "+f"(d[2]), "+f"(d[3])
        : "r"(a[0]), "r"(a[1]), "r"(a[2]), "r"(a[3]),
          "r"(b[0]), "r"(b[1]));
}

// ---------------------------------------------------------------------------
// Main GEMM: 512 threads, tile 128x128x16, 16 warps (4x4), warp tile 32x32.
// A2,B2 pre-split float2. C = alpha*A@B (+bias)(+gelu)(+resid); out plain or
// split. causalSkip skips blocks with bx > by. threeTerm: 3-term split-tf32
// (fp32-accurate) vs 2-term (B tf32-rounded; head GEMM only).
// M%128==0, K%16==0; N guarded (all N%64==0).
// ---------------------------------------------------------------------------
__global__ void __launch_bounds__(512)
gemm512(const float2* __restrict__ A, const float2* __restrict__ Bp,
        float* __restrict__ Cp,
        int M, int N, int K, int lda, int ldb, int ldc,
        long long sAb, long long sAh, long long sBb, long long sBh,
        long long sCb, long long sCh, int nH,
        const float* __restrict__ bias, const float* __restrict__ resid,
        float alpha, int doGelu, int transB, int outSplit, int causalSkip,
        int threeTerm)
{
    if (causalSkip && blockIdx.x > blockIdx.y) return;
    extern __shared__ float2 smbuf[];

    int bz = blockIdx.z;
    int bb = bz / nH, hh = bz - bb * nH;
    A  += bb * sAb + hh * sAh;
    Bp += bb * sBb + hh * sBh;
    const float* Rp = resid ? (resid + bb * sCb + hh * sCh) : (const float*)0;

    int m0   = blockIdx.y << 7;
    int n0   = blockIdx.x << 7;
    int tid  = threadIdx.x;
    int lane = tid & 31;
    int wid  = tid >> 5;
    int wm   = (wid & 3) << 5;      // 0,32,64,96
    int wn   = (wid >> 2) << 5;     // 0,32,64,96

    float acc[2][4][4];
    #pragma unroll
    for (int a = 0; a < 2; a++)
        #pragma unroll
        for (int b = 0; b < 4; b++)
            #pragma unroll
            for (int j = 0; j < 4; j++) acc[a][b][j] = 0.f;

    // loader patterns (float2 element units)
    const int la_m = tid >> 2;              // 0..127
    const int la_k = (tid & 3) << 2;        // 0,4,8,12
    const int lb_k = tid >> 5;              // 0..15
    const int lb_n = (tid & 31) << 2;       // 0..124

    float4 ra[2], rb[2];
    const int nk = K >> 4;

    auto LOAD = [&](int k0) {
        {
            const float4* p = (const float4*)(A + (size_t)(m0 + la_m) * lda + (k0 + la_k));
            ra[0] = p[0]; ra[1] = p[1];
        }
        if (transB) {
            if (n0 + la_m < N) {
                const float4* p = (const float4*)(Bp + (size_t)(n0 + la_m) * ldb + (k0 + la_k));
                rb[0] = p[0]; rb[1] = p[1];
            } else {
                rb[0] = make_float4(0.f,0.f,0.f,0.f);
                rb[1] = make_float4(0.f,0.f,0.f,0.f);
            }
        } else {
            if (n0 + lb_n < N) {
                const float4* p = (const float4*)(Bp + (size_t)(k0 + lb_k) * ldb + (n0 + lb_n));
                rb[0] = p[0]; rb[1] = p[1];
            } else {
                rb[0] = make_float4(0.f,0.f,0.f,0.f);
                rb[1] = make_float4(0.f,0.f,0.f,0.f);
            }
        }
    };

    auto STORE = [&](int s) {
        float2* As = smbuf + s * STG;
        float2* Bs = As + KT * P;
        As[(la_k + 0) * P + la_m] = make_float2(ra[0].x, ra[0].y);
        As[(la_k + 1) * P + la_m] = make_float2(ra[0].z, ra[0].w);
        As[(la_k + 2) * P + la_m] = make_float2(ra[1].x, ra[1].y);
        As[(la_k + 3) * P + la_m] = make_float2(ra[1].z, ra[1].w);
        if (transB) {
            Bs[(la_k + 0) * P + la_m] = make_float2(rb[0].x, rb[0].y);
            Bs[(la_k + 1) * P + la_m] = make_float2(rb[0].z, rb[0].w);
            Bs[(la_k + 2) * P + la_m] = make_float2(rb[1].x, rb[1].y);
            Bs[(la_k + 3) * P + la_m] = make_float2(rb[1].z, rb[1].w);
        } else {
            *(float4*)&Bs[lb_k * P + lb_n]     = rb[0];
            *(float4*)&Bs[lb_k * P + lb_n + 2] = rb[1];
        }
    };

    LOAD(0);
    STORE(0);
    __syncthreads();

    for (int t = 0; t < nk; t++) {
        if (t + 1 < nk) LOAD((t + 1) << 4);

        const float2* As = smbuf + (t & 1) * STG;
        const float2* Bs = As + KT * P;

        #pragma unroll
        for (int kk = 0; kk < 16; kk += 8) {
            int ck = kk + (lane & 3);
            int qd = lane >> 2;
            float2 af[2][4];
            #pragma unroll
            for (int mt = 0; mt < 2; mt++) {
                int r = wm + (mt << 4) + qd;
                af[mt][0] = As[ck * P + r];
                af[mt][1] = As[ck * P + r + 8];
                af[mt][2] = As[(ck + 4) * P + r];
                af[mt][3] = As[(ck + 4) * P + r + 8];
            }
            float2 bf[4][2];
            #pragma unroll
            for (int nt = 0; nt < 4; nt++) {
                int cn = wn + (nt << 3) + qd;
                bf[nt][0] = Bs[ck * P + cn];
                bf[nt][1] = Bs[(ck + 4) * P + cn];
            }
            #pragma unroll
            for (int mt = 0; mt < 2; mt++) {
                unsigned ah[4], al[4];
                #pragma unroll
                for (int i2 = 0; i2 < 4; i2++) {
                    ah[i2] = __float_as_uint(af[mt][i2].x);
                    al[i2] = __float_as_uint(af[mt][i2].y);
                }
                #pragma unroll
                for (int nt = 0; nt < 4; nt++) {
                    unsigned bh[2] = {__float_as_uint(bf[nt][0].x), __float_as_uint(bf[nt][1].x)};
                    unsigned bl[2] = {__float_as_uint(bf[nt][0].y), __float_as_uint(bf[nt][1].y)};
                    mma_tf32(acc[mt][nt], ah, bh);
                    mma_tf32(acc[mt][nt], ah, bl);
                    if (threeTerm) mma_tf32(acc[mt][nt], al, bh);
                }
            }
        }

        if (t + 1 < nk) STORE((t + 1) & 1);
        __syncthreads();
    }

    // ---- epilogue ----
    float*  Co = Cp + bb * sCb + hh * sCh;
    float2* C2 = (float2*)Cp + bb * sCb + hh * sCh;
    #pragma unroll
    for (int mt = 0; mt < 2; mt++) {
        #pragma unroll
        for (int nt = 0; nt < 4; nt++) {
            int row = m0 + wm + (mt << 4) + (lane >> 2);
            int col = n0 + wn + (nt << 3) + ((lane & 3) << 1);
            #pragma unroll
            for (int j = 0; j < 4; j++) {
                int r = row + ((j & 2) ? 8 : 0);
                int c = col + (j & 1);
                if (c < N) {
                    float v2 = acc[mt][nt][j] * alpha;
                    if (bias) v2 += bias[c];
                    if (doGelu) v2 = 0.5f * v2 * (1.f + erff(v2 * 0.70710678118654752f));
                    if (Rp) v2 += Rp[(size_t)r * ldc + c];
                    if (outSplit) C2[(size_t)r * ldc + c] = tf32_split2(v2);
                    else          Co[(size_t)r * ldc + c] = v2;
                }
            }
        }
    }
}

// ---------------------------------------------------------------------------
// AV GEMM: o[b,h] = P[1024,1024] @ V[1024,64]. 256 threads, warp tile 16x64
// (8 warps x 1). A is PLAIN float (att), split during smem store (each P tile
// loaded exactly once). K clamped causally per block row. Output split.
// ---------------------------------------------------------------------------
__global__ void __launch_bounds__(256)
gemm_av(const float* __restrict__ A, const float2* __restrict__ Bp,
        float2* __restrict__ Cp,
        int K, int lda, int ldb, int ldc,
        long long sAb, long long sAh, long long sBb, long long sBh,
        long long sCb, long long sCh, int nH)
{
    extern __shared__ float2 smbuf[];
    constexpr int N = HS_;

    int bz = blockIdx.z;
    int bb = bz / nH, hh = bz - bb * nH;
    A  += bb * sAb + hh * sAh;
    Bp += bb * sBb + hh * sBh;
    float2* C2 = Cp + bb * sCb + hh * sCh;

    int m0   = blockIdx.y << 7;
    int tid  = threadIdx.x;
    int lane = tid & 31;
    int wid  = tid >> 5;
    int wm   = wid << 4;

    int K_eff = m0 + 128;           // causal clamp
    if (K_eff > K) K_eff = K;
    const int nk = K_eff >> 4;

    float acc[8][4];
    #pragma unroll
    for (int b = 0; b < 8; b++)
        #pragma unroll
        for (int j = 0; j < 4; j++) acc[b][j] = 0.f;

    const int la_m = tid >> 2;
    const int la_k = (tid & 3) << 2;
    const int lb_k = tid >> 5;
    const int lb_n = (tid & 31) << 2;

    float4 ra[2], rb[2][2];

    auto LOAD = [&](int k0) {
        #pragma unroll
        for (int j = 0; j < 2; j++) {
            int m = la_m + (j << 6);
            ra[j] = *(const float4*)(A + (size_t)(m0 + m) * lda + (k0 + la_k));
        }
        #pragma unroll
        for (int j = 0; j < 2; j++) {
            int kk = lb_k + (j << 3);
            if (lb_n < N) {
                const float4* p = (const float4*)(Bp + (size_t)(k0 + kk) * ldb + lb_n);
                rb[j][0] = p[0]; rb[j][1] = p[1];
            } else {
                rb[j][0] = make_float4(0.f,0.f,0.f,0.f);
                rb[j][1] = make_float4(0.f,0.f,0.f,0.f);
            }
        }
    };

    auto STORE = [&](int s) {
        float2* As = smbuf + s * STG;
        float2* Bs = As + KT * P;
        #pragma unroll
        for (int j = 0; j < 2; j++) {
            int m = la_m + (j << 6);
            float v[4] = {ra[j].x, ra[j].y, ra[j].z, ra[j].w};
            #pragma unroll
            for (int q = 0; q < 4; q++)
                As[(la_k + q) * P + m] = tf32_split2(v[q]);
        }
        #pragma unroll
        for (int j = 0; j < 2; j++) {
            int kk = lb_k + (j << 3);
            *(float4*)&Bs[kk * P + lb_n]     = rb[j][0];
            *(float4*)&Bs[kk * P + lb_n + 2] = rb[j][1];
        }
    };

    LOAD(0);
    STORE(0);
    __syncthreads();

    for (int t = 0; t < nk; t++) {
        if (t + 1 < nk) LOAD((t + 1) << 4);

        const float2* As = smbuf + (t & 1) * STG;
        const float2* Bs = As + KT * P;

        #pragma unroll
        for (int kk = 0; kk < 16; kk += 8) {
            int ck = kk + (lane & 3);
            int qd = lane >> 2;
            float2 af[4];
            {
                int r = wm + qd;
                af[0] = As[ck * P + r];
                af[1] = As[ck * P + r + 8];
                af[2] = As[(ck + 4) * P + r];
                af[3] = As[(ck + 4) * P + r + 8];
            }
            unsigned ah[4], al[4];
            #pragma unroll
            for (int i2 = 0; i2 < 4; i2++) {
                ah[i2] = __float_as_uint(af[i2].x);
                al[i2] = __float_as_uint(af[i2].y);
            }
            #pragma unroll
            for (int nt = 0; nt < 8; nt++) {
                int cn = (nt << 3) + qd;
                float2 b0 = Bs[ck * P + cn];
                float2 b1 = Bs[(ck + 4) * P + cn];
                unsigned bh[2] = {__float_as_uint(b0.x), __float_as_uint(b1.x)};
                unsigned bl[2] = {__float_as_uint(b0.y), __float_as_uint(b1.y)};
                mma_tf32(acc[nt], ah, bh);
                mma_tf32(acc[nt], ah, bl);
                mma_tf32(acc[nt], al, bh);
            }
        }

        if (t + 1 < nk) STORE((t + 1) & 1);
        __syncthreads();
    }

    #pragma unroll
    for (int nt = 0; nt < 8; nt++) {
        int row = m0 + wm + (lane >> 2);
        int col = (nt << 3) + ((lane & 3) << 1);
        #pragma unroll
        for (int j = 0; j < 4; j++) {
            int r = row + ((j & 2) ? 8 : 0);
            int c = col + (j & 1);
            if (c < N)
                C2[(size_t)r * ldc + c] = tf32_split2(acc[nt][j]);
        }
    }
}

// ---------------------------------------------------------------------------
// Elementwise split (batched over all layers)
// ---------------------------------------------------------------------------
__global__ void split_k(const float* __restrict__ src, float2* __restrict__ dst, int n4)
{
    int i = blockIdx.x * 256 + threadIdx.x;
    if (i < n4) {
        float4 v = ((const float4*)src)[i];
        dst[4 * i + 0] = tf32_split2(v.x);
        dst[4 * i + 1] = tf32_split2(v.y);
        dst[4 * i + 2] = tf32_split2(v.z);
        dst[4 * i + 3] = tf32_split2(v.w);
    }
}

// Pack Wq/Wk/Wv [L,C,C] into split Wcat2 [L][C][3C], all layers at once.
__global__ void pack_qkv_split(const float* __restrict__ Wq, const float* __restrict__ Wk,
                               const float* __restrict__ Wv, float2* __restrict__ Wcat)
{
    int i = blockIdx.x * 256 + threadIdx.x;
    if (i < L_ * C_ * C_) {
        int l = i / (C_ * C_);
        int r = i - l * (C_ * C_);
        int k = r / C_, j = r - k * C_;
        float2* W = Wcat + (size_t)l * C_ * C3_;
        W[(size_t)k * C3_ + j]          = tf32_split2(Wq[i]);
        W[(size_t)k * C3_ + C_ + j]     = tf32_split2(Wk[i]);
        W[(size_t)k * C3_ + 2 * C_ + j] = tf32_split2(Wv[i]);
    }
}

// ---------------------------------------------------------------------------
// LayerNorm (biased variance, eps=1e-5) -> split float2 output
// ---------------------------------------------------------------------------
__global__ void layernorm_split(const float* __restrict__ x, const float* __restrict__ g,
                                const float* __restrict__ b, float2* __restrict__ y)
{
    int row = blockIdx.x;
    const float* xr = x + (size_t)row * C_;
    float2* yr      = y + (size_t)row * C_;
    int tid = threadIdx.x;
    float s = 0.f, s2 = 0.f;
    for (int c = tid; c < C_; c += 256) { float v = xr[c]; s += v; s2 += v * v; }
    __shared__ float shs[8], shs2[8];
    #pragma unroll
    for (int o = 16; o; o >>= 1) {
        s  += __shfl_xor_sync(0xffffffffu, s,  o);
        s2 += __shfl_xor_sync(0xffffffffu, s2, o);
    }
    if ((tid & 31) == 0) { shs[tid >> 5] = s; shs2[tid >> 5] = s2; }
    __syncthreads();
    float ts = 0.f, ts2 = 0.f;
    #pragma unroll
    for (int i = 0; i < 8; i++) { ts += shs[i]; ts2 += shs2[i]; }
    float mean = ts * (1.f / C_);
    float var  = ts2 * (1.f / C_) - mean * mean;
    float rstd = rsqrtf(var + 1e-5f);
    for (int c = tid; c < C_; c += 256)
        yr[c] = tf32_split2((xr[c] - mean) * rstd * g[c] + b[c]);
}

// ---------------------------------------------------------------------------
// Causal softmax in place; reads valid prefix, writes to next 128 boundary.
// ---------------------------------------------------------------------------
__global__ void softmax_causal(float* __restrict__ att)
{
    int row = blockIdx.x;             // b*H*T + h*T + q
    int q   = row & (T_ - 1);
    float* a = att + (size_t)row * T_;
    int len  = q + 1;
    int wlim = ((q >> 7) + 1) << 7;
    int tid  = threadIdx.x;
    __shared__ float sh[8];

    float r[4];
    #pragma unroll
    for (int i = 0; i < 4; i++) {
        int c = tid + (i << 8);
        r[i] = (c < len) ? a[c] : -3.0e38f;
    }
    float mx = fmaxf(fmaxf(r[0], r[1]), fmaxf(r[2], r[3]));
    #pragma unroll
    for (int o = 16; o; o >>= 1) mx = fmaxf(mx, __shfl_xor_sync(0xffffffffu, mx, o));
    if ((tid & 31) == 0) sh[tid >> 5] = mx;
    __syncthreads();
    mx = sh[0];
    #pragma unroll
    for (int i = 1; i < 8; i++) mx = fmaxf(mx, sh[i]);
    __syncthreads();

    float s = 0.f;
    #pragma unroll
    for (int i = 0; i < 4; i++) {
        int c = tid + (i << 8);
        r[i] = (c < len) ? expf(r[i] - mx) : 0.f;
        s += r[i];
    }
    #pragma unroll
    for (int o = 16; o; o >>= 1) s += __shfl_xor_sync(0xffffffffu, s, o);
    if ((tid & 31) == 0) sh[tid >> 5] = s;
    __syncthreads();
    float tot = 0.f;
    #pragma unroll
    for (int i = 0; i < 8; i++) tot += sh[i];
    float inv = 1.f / tot;

    #pragma unroll
    for (int i = 0; i < 4; i++) {
        int c = tid + (i << 8);
        if (c < wlim) a[c] = r[i] * inv;
    }
}

// ---------------------------------------------------------------------------
// Embedding
// ---------------------------------------------------------------------------
__global__ void embed_k(const int* __restrict__ idx, const float* __restrict__ tok,
                        const float* __restrict__ pos, float* __restrict__ x)
{
    int r = blockIdx.x;
    int t = r & (T_ - 1);
    int token = idx[r];
    const float* te = tok + (size_t)token * C_;
    const float* pe = pos + (size_t)t * C_;
    float* xr = x + (size_t)r * C_;
    for (int c = threadIdx.x; c < C_; c += 256) xr[c] = te[c] + pe[c];
}

// ---------------------------------------------------------------------------
// Launch
// ---------------------------------------------------------------------------
extern "C" void kernel_launch(void* const* d_in, const int* in_sizes, int n_in,
                              void* d_out, int out_size)
{
    (void)in_sizes; (void)n_in; (void)out_size;
    const int*   idx = (const int*)d_in[0];
    const float* tok = (const float*)d_in[1];
    const float* pos = (const float*)d_in[2];
    const float* Wq  = (const float*)d_in[3];
    const float* Wk  = (const float*)d_in[4];
    const float* Wv  = (const float*)d_in[5];
    const float* Wp  = (const float*)d_in[6];
    const float* bp  = (const float*)d_in[7];
    const float* g1  = (const float*)d_in[8];
    const float* be1 = (const float*)d_in[9];
    const float* g2  = (const float*)d_in[10];
    const float* be2 = (const float*)d_in[11];
    const float* W1  = (const float*)d_in[12];
    const float* bb1 = (const float*)d_in[13];
    const float* W2  = (const float*)d_in[14];
    const float* bb2 = (const float*)d_in[15];
    const float* gf  = (const float*)d_in[16];
    const float* bf  = (const float*)d_in[17];
    const float* Wh  = (const float*)d_in[18];
    const float* bhd = (const float*)d_in[19];
    float* out = (float*)d_out;

    float  *x, *att;
    float2 *h2, *qkv2, *o2, *a12, *wcat2, *wp2, *w12, *w22, *wh2;
    cudaGetSymbolAddress((void**)&x,     g_x);
    cudaGetSymbolAddress((void**)&h2,    g_h2);
    cudaGetSymbolAddress((void**)&qkv2,  g_qkv2);
    cudaGetSymbolAddress((void**)&o2,    g_o2);
    cudaGetSymbolAddress((void**)&a12,   g_a12);
    cudaGetSymbolAddress((void**)&att,   g_att);
    cudaGetSymbolAddress((void**)&wcat2, g_wcat2);
    cudaGetSymbolAddress((void**)&wp2,   g_wp2);
    cudaGetSymbolAddress((void**)&w12,   g_w12);
    cudaGetSymbolAddress((void**)&w22,   g_w22);
    cudaGetSymbolAddress((void**)&wh2,   g_wh2);

    cudaFuncSetAttribute((const void*)gemm512,
                         cudaFuncAttributeMaxDynamicSharedMemorySize, (int)SMEM_BYTES);
    cudaFuncSetAttribute((const void*)gemm_av,
                         cudaFuncAttributeMaxDynamicSharedMemorySize, (int)SMEM_BYTES);

    const float att_scale = 0.03608439182435161f;  // 768^-0.5 (reference uses full C)
    const float* NOF = (const float*)0;

    embed_k<<<BT_, 256>>>(idx, tok, pos, x);

    // --- pre-split all weights (batched over layers) ---
    pack_qkv_split<<<(L_ * C_ * C_ + 255) / 256, 256>>>(Wq, Wk, Wv, wcat2);
    split_k<<<(L_ * C_ * C_  / 4 + 255) / 256, 256>>>(Wp, wp2, L_ * C_ * C_  / 4);
    split_k<<<(L_ * C_ * C4_ / 4 + 255) / 256, 256>>>(W1, w12, L_ * C_ * C4_ / 4);
    split_k<<<(L_ * C4_ * C_ / 4 + 255) / 256, 256>>>(W2, w22, L_ * C4_ * C_ / 4);
    split_k<<<(C_ * V_ / 4 + 255) / 256, 256>>>(Wh, wh2, C_ * V_ / 4);

    dim3 gqkv(C3_ / 128, BT_ / 128, 1);
    dim3 gcc (C_  / 128, BT_ / 128, 1);
    dim3 gsc (T_  / 128, T_  / 128, B_ * H_);
    dim3 gav (1,         T_  / 128, B_ * H_);
    dim3 gf1 (C4_ / 128, BT_ / 128, 1);

    for (int l = 0; l < L_; l++) {
        layernorm_split<<<BT_, 256>>>(x, g1 + l * C_, be1 + l * C_, h2);

        // qkv = h @ Wcat -> split [BT, 3C]
        gemm512<<<gqkv, 512, SMEM_BYTES>>>(h2, wcat2 + (size_t)l * C_ * C3_, (float*)qkv2,
                BT_, C3_, C_, C_, C3_, C3_,
                0, 0, 0, 0, 0, 0, 1, NOF, NOF, 1.f, 0, 0, 1, 0, 1);

        // scores: Q @ K^T per (b,h) -> plain att, upper blocks skipped
        gemm512<<<gsc, 512, SMEM_BYTES>>>(qkv2, qkv2 + C_, att,
                T_, T_, HS_, C3_, C3_, T_,
                (long long)T_ * C3_, (long long)HS_,
                (long long)T_ * C3_, (long long)HS_,
                (long long)H_ * T_ * T_, (long long)T_ * T_, H_,
                NOF, NOF, att_scale, 0, 1, 0, 1, 1);

        softmax_causal<<<B_ * H_ * T_, 256>>>(att);

        // AV: P @ V -> split o (causally clamped K)
        gemm_av<<<gav, 256, SMEM_BYTES>>>(att, qkv2 + 2 * C_, o2,
                T_, T_, C3_, C_,
                (long long)H_ * T_ * T_, (long long)T_ * T_,
                (long long)T_ * C3_, (long long)HS_,
                (long long)T_ * C_, (long long)HS_, H_);

        // x = x + o @ Wproj + bproj (plain out)
        gemm512<<<gcc, 512, SMEM_BYTES>>>(o2, wp2 + (size_t)l * C_ * C_, x,
                BT_, C_, C_, C_, C_, C_,
                0, 0, 0, 0, 0, 0, 1, bp + l * C_, x, 1.f, 0, 0, 0, 0, 1);

        layernorm_split<<<BT_, 256>>>(x, g2 + l * C_, be2 + l * C_, h2);

        // a1 = gelu(h @ W1 + b1) -> split
        gemm512<<<gf1, 512, SMEM_BYTES>>>(h2, w12 + (size_t)l * C_ * C4_, (float*)a12,
                BT_, C4_, C_, C_, C4_, C4_,
                0, 0, 0, 0, 0, 0, 1, bb1 + l * C4_, NOF, 1.f, 1, 0, 1, 0, 1);

        // x = x + a1 @ W2 + b2 (plain out)
        gemm512<<<gcc, 512, SMEM_BYTES>>>(a12, w22 + (size_t)l * C4_ * C_, x,
                BT_, C_, C4_, C4_, C_, C_,
                0, 0, 0, 0, 0, 0, 1, bb2 + l * C_, x, 1.f, 0, 0, 0, 0, 1);
    }

    layernorm_split<<<BT_, 256>>>(x, gf, bf, h2);

    // head: 2-term split (error-terminal GEMM; 33% fewer MMAs)
    dim3 ghd(V_ / 128, BT_ / 128, 1);
    gemm512<<<ghd, 512, SMEM_BYTES>>>(h2, wh2, out,
            BT_, V_, C_, C_, V_, V_,
            0, 0, 0, 0, 0, 0, 1, bhd, NOF, 1.f, 0, 0, 0, 0, 0);
}

// round 10
// speedup vs baseline: 1.1923x; 1.0500x over previous
#include <cuda_runtime.h>
#include <math.h>

// ---------------------------------------------------------------------------
// GPT-2 small forward. fp32 activations; GEMMs use split-tf32 (3xTF32)
// mma.sync on pre-split (hi,lo) float2 operands. 512-thread CTAs, KT=16
// double-buffered tiles, causal-aware attention. Term count is a TEMPLATE
// parameter (3-term in-network, 2-term for the error-terminal head GEMM)
// so the inner MMA loop carries no runtime branch.
// ---------------------------------------------------------------------------

namespace {
constexpr int B_  = 4;
constexpr int T_  = 1024;
constexpr int C_  = 768;
constexpr int H_  = 12;
constexpr int HS_ = 64;
constexpr int L_  = 12;
constexpr int V_  = 32000;
constexpr int BT_ = B_ * T_;
constexpr int C4_ = 4 * C_;
constexpr int C3_ = 3 * C_;

constexpr int KT = 16;              // k per tile
constexpr int P  = 132;             // smem row pitch in float2
constexpr int STG = 2 * KT * P;     // float2 per stage (As + Bs)
constexpr size_t SMEM_BYTES = 2 * STG * sizeof(float2);   // 67584 B
}

// Scratch (no cudaMalloc -> device globals)
__device__ float  g_x   [BT_ * C_];
__device__ float2 g_h2  [BT_ * C_];
__device__ float2 g_qkv2[BT_ * C3_];
__device__ float2 g_o2  [BT_ * C_];
__device__ float2 g_a12 [BT_ * C4_];
__device__ float  g_att [(size_t)B_ * H_ * T_ * T_];
// all-layer pre-split weights
__device__ float2 g_wcat2[(size_t)L_ * C_ * C3_];
__device__ float2 g_wp2  [(size_t)L_ * C_ * C_];
__device__ float2 g_w12  [(size_t)L_ * C_ * C4_];
__device__ float2 g_w22  [(size_t)L_ * C4_ * C_];
__device__ float2 g_wh2  [(size_t)C_ * V_];

// ---------------------------------------------------------------------------
// tf32 helpers
// ---------------------------------------------------------------------------
__device__ __forceinline__ float2 tf32_split2(float x) {
    unsigned h;
    asm("cvt.rna.tf32.f32 %0, %1;" : "=r"(h) : "f"(x));
    float hf = __uint_as_float(h);
    float l  = x - hf;                       // exact in fp32
    unsigned lu;
    asm("cvt.rna.tf32.f32 %0, %1;" : "=r"(lu) : "f"(l));
    return make_float2(hf, __uint_as_float(lu));
}

__device__ __forceinline__ void mma_tf32(float* d, const unsigned* a, const unsigned* b) {
    asm volatile(
        "mma.sync.aligned.m16n8k8.row.col.f32.tf32.tf32.f32 "
        "{%0,%1,%2,%3}, {%4,%5,%6,%7}, {%8,%9}, {%0,%1,%2,%3};"
        : "+f"(d[0]), "+f"(d[1]), "+f"(d[2]), "+f"(d[3])
        : "r"(a[0]), "r"(a[1]), "r"(a[2]), "r"(a[3]),
          "r"(b[0]), "r"(b[1]));
}

// ---------------------------------------------------------------------------
// Main GEMM: 512 threads, tile 128x128x16, 16 warps (4x4), warp tile 32x32.
// A2,B2 pre-split float2. C = alpha*A@B (+bias)(+gelu)(+resid); out plain or
// split. causalSkip skips blocks with bx > by. THREE (template): 3-term
// split-tf32 (fp32-accurate) vs 2-term (B tf32-rounded; head GEMM only).
// M%128==0, K%16==0; N guarded (all N%64==0).
// ---------------------------------------------------------------------------
template<int THREE>
__global__ void __launch_bounds__(512)
gemm512(const float2* __restrict__ A, const float2* __restrict__ Bp,
        float* __restrict__ Cp,
        int M, int N, int K, int lda, int ldb, int ldc,
        long long sAb, long long sAh, long long sBb, long long sBh,
        long long sCb, long long sCh, int nH,
        const float* __restrict__ bias, const float* __restrict__ resid,
        float alpha, int doGelu, int transB, int outSplit, int causalSkip)
{
    if (causalSkip && blockIdx.x > blockIdx.y) return;
    extern __shared__ float2 smbuf[];

    int bz = blockIdx.z;
    int bb = bz / nH, hh = bz - bb * nH;
    A  += bb * sAb + hh * sAh;
    Bp += bb * sBb + hh * sBh;
    const float* Rp = resid ? (resid + bb * sCb + hh * sCh) : (const float*)0;

    int m0   = blockIdx.y << 7;
    int n0   = blockIdx.x << 7;
    int tid  = threadIdx.x;
    int lane = tid & 31;
    int wid  = tid >> 5;
    int wm   = (wid & 3) << 5;      // 0,32,64,96
    int wn   = (wid >> 2) << 5;     // 0,32,64,96

    float acc[2][4][4];
    #pragma unroll
    for (int a = 0; a < 2; a++)
        #pragma unroll
        for (int b = 0; b < 4; b++)
            #pragma unroll
            for (int j = 0; j < 4; j++) acc[a][b][j] = 0.f;

    // loader patterns (float2 element units)
    const int la_m = tid >> 2;              // 0..127
    const int la_k = (tid & 3) << 2;        // 0,4,8,12
    const int lb_k = tid >> 5;              // 0..15
    const int lb_n = (tid & 31) << 2;       // 0..124

    float4 ra[2], rb[2];
    const int nk = K >> 4;

    auto LOAD = [&](int k0) {
        {
            const float4* p = (const float4*)(A + (size_t)(m0 + la_m) * lda + (k0 + la_k));
            ra[0] = p[0]; ra[1] = p[1];
        }
        if (transB) {
            if (n0 + la_m < N) {
                const float4* p = (const float4*)(Bp + (size_t)(n0 + la_m) * ldb + (k0 + la_k));
                rb[0] = p[0]; rb[1] = p[1];
            } else {
                rb[0] = make_float4(0.f,0.f,0.f,0.f);
                rb[1] = make_float4(0.f,0.f,0.f,0.f);
            }
        } else {
            if (n0 + lb_n < N) {
                const float4* p = (const float4*)(Bp + (size_t)(k0 + lb_k) * ldb + (n0 + lb_n));
                rb[0] = p[0]; rb[1] = p[1];
            } else {
                rb[0] = make_float4(0.f,0.f,0.f,0.f);
                rb[1] = make_float4(0.f,0.f,0.f,0.f);
            }
        }
    };

    auto STORE = [&](int s) {
        float2* As = smbuf + s * STG;
        float2* Bs = As + KT * P;
        As[(la_k + 0) * P + la_m] = make_float2(ra[0].x, ra[0].y);
        As[(la_k + 1) * P + la_m] = make_float2(ra[0].z, ra[0].w);
        As[(la_k + 2) * P + la_m] = make_float2(ra[1].x, ra[1].y);
        As[(la_k + 3) * P + la_m] = make_float2(ra[1].z, ra[1].w);
        if (transB) {
            Bs[(la_k + 0) * P + la_m] = make_float2(rb[0].x, rb[0].y);
            Bs[(la_k + 1) * P + la_m] = make_float2(rb[0].z, rb[0].w);
            Bs[(la_k + 2) * P + la_m] = make_float2(rb[1].x, rb[1].y);
            Bs[(la_k + 3) * P + la_m] = make_float2(rb[1].z, rb[1].w);
        } else {
            *(float4*)&Bs[lb_k * P + lb_n]     = rb[0];
            *(float4*)&Bs[lb_k * P + lb_n + 2] = rb[1];
        }
    };

    LOAD(0);
    STORE(0);
    __syncthreads();

    for (int t = 0; t < nk; t++) {
        if (t + 1 < nk) LOAD((t + 1) << 4);

        const float2* As = smbuf + (t & 1) * STG;
        const float2* Bs = As + KT * P;

        #pragma unroll
        for (int kk = 0; kk < 16; kk += 8) {
            int ck = kk + (lane & 3);
            int qd = lane >> 2;
            float2 af[2][4];
            #pragma unroll
            for (int mt = 0; mt < 2; mt++) {
                int r = wm + (mt << 4) + qd;
                af[mt][0] = As[ck * P + r];
                af[mt][1] = As[ck * P + r + 8];
                af[mt][2] = As[(ck + 4) * P + r];
                af[mt][3] = As[(ck + 4) * P + r + 8];
            }
            float2 bf[4][2];
            #pragma unroll
            for (int nt = 0; nt < 4; nt++) {
                int cn = wn + (nt << 3) + qd;
                bf[nt][0] = Bs[ck * P + cn];
                bf[nt][1] = Bs[(ck + 4) * P + cn];
            }
            #pragma unroll
            for (int mt = 0; mt < 2; mt++) {
                unsigned ah[4], al[4];
                #pragma unroll
                for (int i2 = 0; i2 < 4; i2++) {
                    ah[i2] = __float_as_uint(af[mt][i2].x);
                    al[i2] = __float_as_uint(af[mt][i2].y);
                }
                #pragma unroll
                for (int nt = 0; nt < 4; nt++) {
                    unsigned bh[2] = {__float_as_uint(bf[nt][0].x), __float_as_uint(bf[nt][1].x)};
                    unsigned bl[2] = {__float_as_uint(bf[nt][0].y), __float_as_uint(bf[nt][1].y)};
                    mma_tf32(acc[mt][nt], ah, bh);
                    mma_tf32(acc[mt][nt], ah, bl);
                    if (THREE) mma_tf32(acc[mt][nt], al, bh);
                }
            }
        }

        if (t + 1 < nk) STORE((t + 1) & 1);
        __syncthreads();
    }

    // ---- epilogue ----
    float*  Co = Cp + bb * sCb + hh * sCh;
    float2* C2 = (float2*)Cp + bb * sCb + hh * sCh;
    #pragma unroll
    for (int mt = 0; mt < 2; mt++) {
        #pragma unroll
        for (int nt = 0; nt < 4; nt++) {
            int row = m0 + wm + (mt << 4) + (lane >> 2);
            int col = n0 + wn + (nt << 3) + ((lane & 3) << 1);
            #pragma unroll
            for (int j = 0; j < 4; j++) {
                int r = row + ((j & 2) ? 8 : 0);
                int c = col + (j & 1);
                if (c < N) {
                    float v2 = acc[mt][nt][j] * alpha;
                    if (bias) v2 += bias[c];
                    if (doGelu) v2 = 0.5f * v2 * (1.f + erff(v2 * 0.70710678118654752f));
                    if (Rp) v2 += Rp[(size_t)r * ldc + c];
                    if (outSplit) C2[(size_t)r * ldc + c] = tf32_split2(v2);
                    else          Co[(size_t)r * ldc + c] = v2;
                }
            }
        }
    }
}

// ---------------------------------------------------------------------------
// AV GEMM: o[b,h] = P[1024,1024] @ V[1024,64]. 256 threads, warp tile 16x64
// (8 warps x 1). A is PLAIN float (att), split during smem store (each P tile
// loaded exactly once). K clamped causally per block row. Output split.
// ---------------------------------------------------------------------------
__global__ void __launch_bounds__(256)
gemm_av(const float* __restrict__ A, const float2* __restrict__ Bp,
        float2* __restrict__ Cp,
        int K, int lda, int ldb, int ldc,
        long long sAb, long long sAh, long long sBb, long long sBh,
        long long sCb, long long sCh, int nH)
{
    extern __shared__ float2 smbuf[];
    constexpr int N = HS_;

    int bz = blockIdx.z;
    int bb = bz / nH, hh = bz - bb * nH;
    A  += bb * sAb + hh * sAh;
    Bp += bb * sBb + hh * sBh;
    float2* C2 = Cp + bb * sCb + hh * sCh;

    int m0   = blockIdx.y << 7;
    int tid  = threadIdx.x;
    int lane = tid & 31;
    int wid  = tid >> 5;
    int wm   = wid << 4;

    int K_eff = m0 + 128;           // causal clamp
    if (K_eff > K) K_eff = K;
    const int nk = K_eff >> 4;

    float acc[8][4];
    #pragma unroll
    for (int b = 0; b < 8; b++)
        #pragma unroll
        for (int j = 0; j < 4; j++) acc[b][j] = 0.f;

    const int la_m = tid >> 2;
    const int la_k = (tid & 3) << 2;
    const int lb_k = tid >> 5;
    const int lb_n = (tid & 31) << 2;

    float4 ra[2], rb[2][2];

    auto LOAD = [&](int k0) {
        #pragma unroll
        for (int j = 0; j < 2; j++) {
            int m = la_m + (j << 6);
            ra[j] = *(const float4*)(A + (size_t)(m0 + m) * lda + (k0 + la_k));
        }
        #pragma unroll
        for (int j = 0; j < 2; j++) {
            int kk = lb_k + (j << 3);
            if (lb_n < N) {
                const float4* p = (const float4*)(Bp + (size_t)(k0 + kk) * ldb + lb_n);
                rb[j][0] = p[0]; rb[j][1] = p[1];
            } else {
                rb[j][0] = make_float4(0.f,0.f,0.f,0.f);
                rb[j][1] = make_float4(0.f,0.f,0.f,0.f);
            }
        }
    };

    auto STORE = [&](int s) {
        float2* As = smbuf + s * STG;
        float2* Bs = As + KT * P;
        #pragma unroll
        for (int j = 0; j < 2; j++) {
            int m = la_m + (j << 6);
            float v[4] = {ra[j].x, ra[j].y, ra[j].z, ra[j].w};
            #pragma unroll
            for (int q = 0; q < 4; q++)
                As[(la_k + q) * P + m] = tf32_split2(v[q]);
        }
        #pragma unroll
        for (int j = 0; j < 2; j++) {
            int kk = lb_k + (j << 3);
            *(float4*)&Bs[kk * P + lb_n]     = rb[j][0];
            *(float4*)&Bs[kk * P + lb_n + 2] = rb[j][1];
        }
    };

    LOAD(0);
    STORE(0);
    __syncthreads();

    for (int t = 0; t < nk; t++) {
        if (t + 1 < nk) LOAD((t + 1) << 4);

        const float2* As = smbuf + (t & 1) * STG;
        const float2* Bs = As + KT * P;

        #pragma unroll
        for (int kk = 0; kk < 16; kk += 8) {
            int ck = kk + (lane & 3);
            int qd = lane >> 2;
            float2 af[4];
            {
                int r = wm + qd;
                af[0] = As[ck * P + r];
                af[1] = As[ck * P + r + 8];
                af[2] = As[(ck + 4) * P + r];
                af[3] = As[(ck + 4) * P + r + 8];
            }
            unsigned ah[4], al[4];
            #pragma unroll
            for (int i2 = 0; i2 < 4; i2++) {
                ah[i2] = __float_as_uint(af[i2].x);
                al[i2] = __float_as_uint(af[i2].y);
            }
            #pragma unroll
            for (int nt = 0; nt < 8; nt++) {
                int cn = (nt << 3) + qd;
                float2 b0 = Bs[ck * P + cn];
                float2 b1 = Bs[(ck + 4) * P + cn];
                unsigned bh[2] = {__float_as_uint(b0.x), __float_as_uint(b1.x)};
                unsigned bl[2] = {__float_as_uint(b0.y), __float_as_uint(b1.y)};
                mma_tf32(acc[nt], ah, bh);
                mma_tf32(acc[nt], ah, bl);
                mma_tf32(acc[nt], al, bh);
            }
        }

        if (t + 1 < nk) STORE((t + 1) & 1);
        __syncthreads();
    }

    #pragma unroll
    for (int nt = 0; nt < 8; nt++) {
        int row = m0 + wm + (lane >> 2);
        int col = (nt << 3) + ((lane & 3) << 1);
        #pragma unroll
        for (int j = 0; j < 4; j++) {
            int r = row + ((j & 2) ? 8 : 0);
            int c = col + (j & 1);
            if (c < N)
                C2[(size_t)r * ldc + c] = tf32_split2(acc[nt][j]);
        }
    }
}

// ---------------------------------------------------------------------------
// Elementwise split (batched over all layers)
// ---------------------------------------------------------------------------
__global__ void split_k(const float* __restrict__ src, float2* __restrict__ dst, int n4)
{
    int i = blockIdx.x * 256 + threadIdx.x;
    if (i < n4) {
        float4 v = ((const float4*)src)[i];
        dst[4 * i + 0] = tf32_split2(v.x);
        dst[4 * i + 1] = tf32_split2(v.y);
        dst[4 * i + 2] = tf32_split2(v.z);
        dst[4 * i + 3] = tf32_split2(v.w);
    }
}

// Pack Wq/Wk/Wv [L,C,C] into split Wcat2 [L][C][3C], all layers at once.
__global__ void pack_qkv_split(const float* __restrict__ Wq, const float* __restrict__ Wk,
                               const float* __restrict__ Wv, float2* __restrict__ Wcat)
{
    int i = blockIdx.x * 256 + threadIdx.x;
    if (i < L_ * C_ * C_) {
        int l = i / (C_ * C_);
        int r = i - l * (C_ * C_);
        int k = r / C_, j = r - k * C_;
        float2* W = Wcat + (size_t)l * C_ * C3_;
        W[(size_t)k * C3_ + j]          = tf32_split2(Wq[i]);
        W[(size_t)k * C3_ + C_ + j]     = tf32_split2(Wk[i]);
        W[(size_t)k * C3_ + 2 * C_ + j] = tf32_split2(Wv[i]);
    }
}

// ---------------------------------------------------------------------------
// LayerNorm (biased variance, eps=1e-5) -> split float2 output
// ---------------------------------------------------------------------------
__global__ void layernorm_split(const float* __restrict__ x, const float* __restrict__ g,
                                const float* __restrict__ b, float2* __restrict__ y)
{
    int row = blockIdx.x;
    const float* xr = x + (size_t)row * C_;
    float2* yr      = y + (size_t)row * C_;
    int tid = threadIdx.x;
    float s = 0.f, s2 = 0.f;
    for (int c = tid; c < C_; c += 256) { float v = xr[c]; s += v; s2 += v * v; }
    __shared__ float shs[8], shs2[8];
    #pragma unroll
    for (int o = 16; o; o >>= 1) {
        s  += __shfl_xor_sync(0xffffffffu, s,  o);
        s2 += __shfl_xor_sync(0xffffffffu, s2, o);
    }
    if ((tid & 31) == 0) { shs[tid >> 5] = s; shs2[tid >> 5] = s2; }
    __syncthreads();
    float ts = 0.f, ts2 = 0.f;
    #pragma unroll
    for (int i = 0; i < 8; i++) { ts += shs[i]; ts2 += shs2[i]; }
    float mean = ts * (1.f / C_);
    float var  = ts2 * (1.f / C_) - mean * mean;
    float rstd = rsqrtf(var + 1e-5f);
    for (int c = tid; c < C_; c += 256)
        yr[c] = tf32_split2((xr[c] - mean) * rstd * g[c] + b[c]);
}

// ---------------------------------------------------------------------------
// Causal softmax in place; reads valid prefix, writes to next 128 boundary.
// ---------------------------------------------------------------------------
__global__ void softmax_causal(float* __restrict__ att)
{
    int row = blockIdx.x;             // b*H*T + h*T + q
    int q   = row & (T_ - 1);
    float* a = att + (size_t)row * T_;
    int len  = q + 1;
    int wlim = ((q >> 7) + 1) << 7;
    int tid  = threadIdx.x;
    __shared__ float sh[8];

    float r[4];
    #pragma unroll
    for (int i = 0; i < 4; i++) {
        int c = tid + (i << 8);
        r[i] = (c < len) ? a[c] : -3.0e38f;
    }
    float mx = fmaxf(fmaxf(r[0], r[1]), fmaxf(r[2], r[3]));
    #pragma unroll
    for (int o = 16; o; o >>= 1) mx = fmaxf(mx, __shfl_xor_sync(0xffffffffu, mx, o));
    if ((tid & 31) == 0) sh[tid >> 5] = mx;
    __syncthreads();
    mx = sh[0];
    #pragma unroll
    for (int i = 1; i < 8; i++) mx = fmaxf(mx, sh[i]);
    __syncthreads();

    float s = 0.f;
    #pragma unroll
    for (int i = 0; i < 4; i++) {
        int c = tid + (i << 8);
        r[i] = (c < len) ? expf(r[i] - mx) : 0.f;
        s += r[i];
    }
    #pragma unroll
    for (int o = 16; o; o >>= 1) s += __shfl_xor_sync(0xffffffffu, s, o);
    if ((tid & 31) == 0) sh[tid >> 5] = s;
    __syncthreads();
    float tot = 0.f;
    #pragma unroll
    for (int i = 0; i < 8; i++) tot += sh[i];
    float inv = 1.f / tot;

    #pragma unroll
    for (int i = 0; i < 4; i++) {
        int c = tid + (i << 8);
        if (c < wlim) a[c] = r[i] * inv;
    }
}

// ---------------------------------------------------------------------------
// Embedding
// ---------------------------------------------------------------------------
__global__ void embed_k(const int* __restrict__ idx, const float* __restrict__ tok,
                        const float* __restrict__ pos, float* __restrict__ x)
{
    int r = blockIdx.x;
    int t = r & (T_ - 1);
    int token = idx[r];
    const float* te = tok + (size_t)token * C_;
    const float* pe = pos + (size_t)t * C_;
    float* xr = x + (size_t)r * C_;
    for (int c = threadIdx.x; c < C_; c += 256) xr[c] = te[c] + pe[c];
}

// ---------------------------------------------------------------------------
// Launch
// ---------------------------------------------------------------------------
extern "C" void kernel_launch(void* const* d_in, const int* in_sizes, int n_in,
                              void* d_out, int out_size)
{
    (void)in_sizes; (void)n_in; (void)out_size;
    const int*   idx = (const int*)d_in[0];
    const float* tok = (const float*)d_in[1];
    const float* pos = (const float*)d_in[2];
    const float* Wq  = (const float*)d_in[3];
    const float* Wk  = (const float*)d_in[4];
    const float* Wv  = (const float*)d_in[5];
    const float* Wp  = (const float*)d_in[6];
    const float* bp  = (const float*)d_in[7];
    const float* g1  = (const float*)d_in[8];
    const float* be1 = (const float*)d_in[9];
    const float* g2  = (const float*)d_in[10];
    const float* be2 = (const float*)d_in[11];
    const float* W1  = (const float*)d_in[12];
    const float* bb1 = (const float*)d_in[13];
    const float* W2  = (const float*)d_in[14];
    const float* bb2 = (const float*)d_in[15];
    const float* gf  = (const float*)d_in[16];
    const float* bf  = (const float*)d_in[17];
    const float* Wh  = (const float*)d_in[18];
    const float* bhd = (const float*)d_in[19];
    float* out = (float*)d_out;

    float  *x, *att;
    float2 *h2, *qkv2, *o2, *a12, *wcat2, *wp2, *w12, *w22, *wh2;
    cudaGetSymbolAddress((void**)&x,     g_x);
    cudaGetSymbolAddress((void**)&h2,    g_h2);
    cudaGetSymbolAddress((void**)&qkv2,  g_qkv2);
    cudaGetSymbolAddress((void**)&o2,    g_o2);
    cudaGetSymbolAddress((void**)&a12,   g_a12);
    cudaGetSymbolAddress((void**)&att,   g_att);
    cudaGetSymbolAddress((void**)&wcat2, g_wcat2);
    cudaGetSymbolAddress((void**)&wp2,   g_wp2);
    cudaGetSymbolAddress((void**)&w12,   g_w12);
    cudaGetSymbolAddress((void**)&w22,   g_w22);
    cudaGetSymbolAddress((void**)&wh2,   g_wh2);

    cudaFuncSetAttribute((const void*)gemm512<1>,
                         cudaFuncAttributeMaxDynamicSharedMemorySize, (int)SMEM_BYTES);
    cudaFuncSetAttribute((const void*)gemm512<0>,
                         cudaFuncAttributeMaxDynamicSharedMemorySize, (int)SMEM_BYTES);
    cudaFuncSetAttribute((const void*)gemm_av,
                         cudaFuncAttributeMaxDynamicSharedMemorySize, (int)SMEM_BYTES);

    const float att_scale = 0.03608439182435161f;  // 768^-0.5 (reference uses full C)
    const float* NOF = (const float*)0;

    embed_k<<<BT_, 256>>>(idx, tok, pos, x);

    // --- pre-split all weights (batched over layers) ---
    pack_qkv_split<<<(L_ * C_ * C_ + 255) / 256, 256>>>(Wq, Wk, Wv, wcat2);
    split_k<<<(L_ * C_ * C_  / 4 + 255) / 256, 256>>>(Wp, wp2, L_ * C_ * C_  / 4);
    split_k<<<(L_ * C_ * C4_ / 4 + 255) / 256, 256>>>(W1, w12, L_ * C_ * C4_ / 4);
    split_k<<<(L_ * C4_ * C_ / 4 + 255) / 256, 256>>>(W2, w22, L_ * C4_ * C_ / 4);
    split_k<<<(C_ * V_ / 4 + 255) / 256, 256>>>(Wh, wh2, C_ * V_ / 4);

    dim3 gqkv(C3_ / 128, BT_ / 128, 1);
    dim3 gcc (C_  / 128, BT_ / 128, 1);
    dim3 gsc (T_  / 128, T_  / 128, B_ * H_);
    dim3 gav (1,         T_  / 128, B_ * H_);
    dim3 gf1 (C4_ / 128, BT_ / 128, 1);

    for (int l = 0; l < L_; l++) {
        layernorm_split<<<BT_, 256>>>(x, g1 + l * C_, be1 + l * C_, h2);

        // qkv = h @ Wcat -> split [BT, 3C]
        gemm512<1><<<gqkv, 512, SMEM_BYTES>>>(h2, wcat2 + (size_t)l * C_ * C3_, (float*)qkv2,
                BT_, C3_, C_, C_, C3_, C3_,
                0, 0, 0, 0, 0, 0, 1, NOF, NOF, 1.f, 0, 0, 1, 0);

        // scores: Q @ K^T per (b,h) -> plain att, upper blocks skipped
        gemm512<1><<<gsc, 512, SMEM_BYTES>>>(qkv2, qkv2 + C_, att,
                T_, T_, HS_, C3_, C3_, T_,
                (long long)T_ * C3_, (long long)HS_,
                (long long)T_ * C3_, (long long)HS_,
                (long long)H_ * T_ * T_, (long long)T_ * T_, H_,
                NOF, NOF, att_scale, 0, 1, 0, 1);

        softmax_causal<<<B_ * H_ * T_, 256>>>(att);

        // AV: P @ V -> split o (causally clamped K)
        gemm_av<<<gav, 256, SMEM_BYTES>>>(att, qkv2 + 2 * C_, o2,
                T_, T_, C3_, C_,
                (long long)H_ * T_ * T_, (long long)T_ * T_,
                (long long)T_ * C3_, (long long)HS_,
                (long long)T_ * C_, (long long)HS_, H_);

        // x = x + o @ Wproj + bproj (plain out)
        gemm512<1><<<gcc, 512, SMEM_BYTES>>>(o2, wp2 + (size_t)l * C_ * C_, x,
                BT_, C_, C_, C_, C_, C_,
                0, 0, 0, 0, 0, 0, 1, bp + l * C_, x, 1.f, 0, 0, 0, 0);

        layernorm_split<<<BT_, 256>>>(x, g2 + l * C_, be2 + l * C_, h2);

        // a1 = gelu(h @ W1 + b1) -> split
        gemm512<1><<<gf1, 512, SMEM_BYTES>>>(h2, w12 + (size_t)l * C_ * C4_, (float*)a12,
                BT_, C4_, C_, C_, C4_, C4_,
                0, 0, 0, 0, 0, 0, 1, bb1 + l * C4_, NOF, 1.f, 1, 0, 1, 0);

        // x = x + a1 @ W2 + b2 (plain out)
        gemm512<1><<<gcc, 512, SMEM_BYTES>>>(a12, w22 + (size_t)l * C4_ * C_, x,
                BT_, C_, C4_, C4_, C_, C_,
                0, 0, 0, 0, 0, 0, 1, bb2 + l * C_, x, 1.f, 0, 0, 0, 0);
    }

    layernorm_split<<<BT_, 256>>>(x, gf, bf, h2);

    // head: 2-term split (error-terminal GEMM; 33% fewer MMAs)
    dim3 ghd(V_ / 128, BT_ / 128, 1);
    gemm512<0><<<ghd, 512, SMEM_BYTES>>>(h2, wh2, out,
            BT_, V_, C_, C_, V_, V_,
            0, 0, 0, 0, 0, 0, 1, bhd, NOF, 1.f, 0, 0, 0, 0);
}

// round 11
// speedup vs baseline: 1.8875x; 1.5831x over previous
#include <cuda_runtime.h>
#include <cuda_bf16.h>
#include <math.h>

// ---------------------------------------------------------------------------
// GPT-2 small forward. fp32 activations; GEMMs use split-bf16 (3xBF16)
// mma.sync.m16n8k16 on pre-split (hi,lo) operands stored as u32 per element
// (hi16 | lo16<<16). Staging packs k-pairs via PRMT; hot loop is pure
// LDS.64 + MMA. 512-thread CTAs, KT=16 double-buffered, causal attention.
// ---------------------------------------------------------------------------

namespace {
constexpr int B_  = 4;
constexpr int T_  = 1024;
constexpr int C_  = 768;
constexpr int H_  = 12;
constexpr int HS_ = 64;
constexpr int L_  = 12;
constexpr int V_  = 32000;
constexpr int BT_ = B_ * T_;
constexpr int C4_ = 4 * C_;
constexpr int C3_ = 3 * C_;

constexpr int KT  = 16;                 // k per tile
constexpr int K2T = KT / 2;             // k-pairs per tile (8)
constexpr int P2  = 132;                // smem row pitch in uint2
constexpr int STG2 = 2 * K2T * P2;      // uint2 per stage (As + Bs)
constexpr size_t SMEM_BYTES = 2 * STG2 * sizeof(uint2);   // 33792 B
}

// Scratch (no cudaMalloc -> device globals)
__device__ float    g_x   [BT_ * C_];
__device__ unsigned g_h2  [BT_ * C_];
__device__ unsigned g_qkv2[BT_ * C3_];
__device__ unsigned g_o2  [BT_ * C_];
__device__ unsigned g_a12 [BT_ * C4_];
__device__ float    g_att [(size_t)B_ * H_ * T_ * T_];
// all-layer pre-split weights (u32 per element)
__device__ unsigned g_wcat2[(size_t)L_ * C_ * C3_];
__device__ unsigned g_wp2  [(size_t)L_ * C_ * C_];
__device__ unsigned g_w12  [(size_t)L_ * C_ * C4_];
__device__ unsigned g_w22  [(size_t)L_ * C4_ * C_];
__device__ unsigned g_wh2  [(size_t)C_ * V_];

// ---------------------------------------------------------------------------
// bf16 split helpers: u32 = hi16 | (lo16 << 16), hi = bf16(x), lo = bf16(x-hi)
// ---------------------------------------------------------------------------
__device__ __forceinline__ unsigned splitbf(float x) {
    __nv_bfloat16 h = __float2bfloat16(x);
    float hf = __bfloat162float(h);
    __nv_bfloat16 l = __float2bfloat16(x - hf);
    return (unsigned)__bfloat16_as_ushort(h) |
           ((unsigned)__bfloat16_as_ushort(l) << 16);
}

// pack two adjacent-k elements into (hipair, lopair) bf16x2 registers
// e0 = element k (hi in b0b1, lo in b2b3), e1 = element k+1
#define HIPAIR(e0, e1) __byte_perm((e0), (e1), 0x5410)
#define LOPAIR(e0, e1) __byte_perm((e0), (e1), 0x7632)

__device__ __forceinline__ void mma_bf16(float* d, const unsigned* a,
                                         unsigned b0, unsigned b1) {
    asm volatile(
        "mma.sync.aligned.m16n8k16.row.col.f32.bf16.bf16.f32 "
        "{%0,%1,%2,%3}, {%4,%5,%6,%7}, {%8,%9}, {%0,%1,%2,%3};"
        : "+f"(d[0]), "+f"(d[1]), "+f"(d[2]), "+f"(d[3])
        : "r"(a[0]), "r"(a[1]), "r"(a[2]), "r"(a[3]),
          "r"(b0), "r"(b1));
}

// ---------------------------------------------------------------------------
// Main GEMM: 512 threads, tile 128x128x16, 16 warps (4x4), warp tile 32x32.
// A,B are u32 (hi,lo) elementwise. C = alpha*A@B (+bias)(+gelu)(+resid);
// out plain float or split u32. causalSkip skips blocks with bx > by.
// 3-term split-bf16 everywhere. M%128==0, K%16==0, N%128==0 here.
// Smem: [k2][row] uint2 {hipair, lopair}.
// ---------------------------------------------------------------------------
__global__ void __launch_bounds__(512)
gemmb(const unsigned* __restrict__ A, const unsigned* __restrict__ Bp,
      float* __restrict__ Cp,
      int M, int N, int K, int lda, int ldb, int ldc,
      long long sAb, long long sAh, long long sBb, long long sBh,
      long long sCb, long long sCh, int nH,
      const float* __restrict__ bias, const float* __restrict__ resid,
      float alpha, int doGelu, int transB, int outSplit, int causalSkip)
{
    if (causalSkip && blockIdx.x > blockIdx.y) return;
    extern __shared__ uint2 smbuf[];

    int bz = blockIdx.z;
    int bb = bz / nH, hh = bz - bb * nH;
    A  += bb * sAb + hh * sAh;
    Bp += bb * sBb + hh * sBh;
    const float* Rp = resid ? (resid + bb * sCb + hh * sCh) : (const float*)0;

    int m0   = blockIdx.y << 7;
    int n0   = blockIdx.x << 7;
    int tid  = threadIdx.x;
    int lane = tid & 31;
    int wid  = tid >> 5;
    int wm   = (wid & 3) << 5;      // 0,32,64,96
    int wn   = (wid >> 2) << 5;     // 0,32,64,96

    float acc[2][4][4];
    #pragma unroll
    for (int a = 0; a < 2; a++)
        #pragma unroll
        for (int b = 0; b < 4; b++)
            #pragma unroll
            for (int j = 0; j < 4; j++) acc[a][b][j] = 0.f;

    // loader patterns
    const int la_m  = tid >> 2;             // 0..127
    const int la_k  = (tid & 3) << 2;       // 0,4,8,12 (4 consecutive k)
    const int lb_k2 = tid >> 6;             // 0..7 (k-pair index)
    const int lb_n  = (tid & 63) << 1;      // 0..126 (2 consecutive n)

    uint4 ra, rbT; uint2 rb0, rb1;
    const int nk = K >> 4;

    auto LOAD = [&](int k0) {
        ra = *(const uint4*)(A + (size_t)(m0 + la_m) * lda + (k0 + la_k));
        if (transB) {
            if (n0 + la_m < N)
                rbT = *(const uint4*)(Bp + (size_t)(n0 + la_m) * ldb + (k0 + la_k));
            else rbT = make_uint4(0u,0u,0u,0u);
        } else {
            if (n0 + lb_n < N) {
                rb0 = *(const uint2*)(Bp + (size_t)(k0 + 2*lb_k2)     * ldb + (n0 + lb_n));
                rb1 = *(const uint2*)(Bp + (size_t)(k0 + 2*lb_k2 + 1) * ldb + (n0 + lb_n));
            } else { rb0 = make_uint2(0u,0u); rb1 = make_uint2(0u,0u); }
        }
    };

    auto STORE = [&](int s) {
        uint2* As = smbuf + s * STG2;
        uint2* Bs = As + K2T * P2;
        int k2 = la_k >> 1;   // 0,2,4,6
        As[(k2    ) * P2 + la_m] = make_uint2(HIPAIR(ra.x, ra.y), LOPAIR(ra.x, ra.y));
        As[(k2 + 1) * P2 + la_m] = make_uint2(HIPAIR(ra.z, ra.w), LOPAIR(ra.z, ra.w));
        if (transB) {
            Bs[(k2    ) * P2 + la_m] = make_uint2(HIPAIR(rbT.x, rbT.y), LOPAIR(rbT.x, rbT.y));
            Bs[(k2 + 1) * P2 + la_m] = make_uint2(HIPAIR(rbT.z, rbT.w), LOPAIR(rbT.z, rbT.w));
        } else {
            Bs[lb_k2 * P2 + lb_n    ] = make_uint2(HIPAIR(rb0.x, rb1.x), LOPAIR(rb0.x, rb1.x));
            Bs[lb_k2 * P2 + lb_n + 1] = make_uint2(HIPAIR(rb0.y, rb1.y), LOPAIR(rb0.y, rb1.y));
        }
    };

    LOAD(0);
    STORE(0);
    __syncthreads();

    for (int t = 0; t < nk; t++) {
        if (t + 1 < nk) LOAD((t + 1) << 4);

        const uint2* As = smbuf + (t & 1) * STG2;
        const uint2* Bs = As + K2T * P2;

        int k2q = lane & 3;
        int qd  = lane >> 2;
        uint2 aA[2][4];
        #pragma unroll
        for (int mt = 0; mt < 2; mt++) {
            int r = wm + (mt << 4) + qd;
            aA[mt][0] = As[ k2q      * P2 + r];
            aA[mt][1] = As[ k2q      * P2 + r + 8];
            aA[mt][2] = As[(k2q + 4) * P2 + r];
            aA[mt][3] = As[(k2q + 4) * P2 + r + 8];
        }
        uint2 bB[4][2];
        #pragma unroll
        for (int nt = 0; nt < 4; nt++) {
            int cn = wn + (nt << 3) + qd;
            bB[nt][0] = Bs[ k2q      * P2 + cn];
            bB[nt][1] = Bs[(k2q + 4) * P2 + cn];
        }
        #pragma unroll
        for (int mt = 0; mt < 2; mt++) {
            unsigned ah[4] = {aA[mt][0].x, aA[mt][1].x, aA[mt][2].x, aA[mt][3].x};
            unsigned al[4] = {aA[mt][0].y, aA[mt][1].y, aA[mt][2].y, aA[mt][3].y};
            #pragma unroll
            for (int nt = 0; nt < 4; nt++) {
                mma_bf16(acc[mt][nt], ah, bB[nt][0].x, bB[nt][1].x);  // hi*hi
                mma_bf16(acc[mt][nt], ah, bB[nt][0].y, bB[nt][1].y);  // hi*lo
                mma_bf16(acc[mt][nt], al, bB[nt][0].x, bB[nt][1].x);  // lo*hi
            }
        }

        if (t + 1 < nk) STORE((t + 1) & 1);
        __syncthreads();
    }

    // ---- epilogue ----
    float*    Co = Cp + bb * sCb + hh * sCh;
    unsigned* Cu = (unsigned*)Cp + bb * sCb + hh * sCh;
    #pragma unroll
    for (int mt = 0; mt < 2; mt++) {
        #pragma unroll
        for (int nt = 0; nt < 4; nt++) {
            int row = m0 + wm + (mt << 4) + (lane >> 2);
            int col = n0 + wn + (nt << 3) + ((lane & 3) << 1);
            #pragma unroll
            for (int j = 0; j < 4; j++) {
                int r = row + ((j & 2) ? 8 : 0);
                int c = col + (j & 1);
                if (c < N) {
                    float v2 = acc[mt][nt][j] * alpha;
                    if (bias) v2 += bias[c];
                    if (doGelu) v2 = 0.5f * v2 * (1.f + erff(v2 * 0.70710678118654752f));
                    if (Rp) v2 += Rp[(size_t)r * ldc + c];
                    if (outSplit) Cu[(size_t)r * ldc + c] = splitbf(v2);
                    else          Co[(size_t)r * ldc + c] = v2;
                }
            }
        }
    }
}

// ---------------------------------------------------------------------------
// AV GEMM: o[b,h] = P[1024,1024] @ V[1024,64]. 256 threads, 8 warps x 1,
// warp tile 16x64. A is PLAIN float (att), split+packed during smem store.
// K clamped causally per block row. Output split u32.
// ---------------------------------------------------------------------------
__global__ void __launch_bounds__(256)
gemm_av(const float* __restrict__ A, const unsigned* __restrict__ Bp,
        unsigned* __restrict__ Cp,
        int K, int lda, int ldb, int ldc,
        long long sAb, long long sAh, long long sBb, long long sBh,
        long long sCb, long long sCh, int nH)
{
    extern __shared__ uint2 smbuf[];
    constexpr int N = HS_;

    int bz = blockIdx.z;
    int bb = bz / nH, hh = bz - bb * nH;
    A  += bb * sAb + hh * sAh;
    Bp += bb * sBb + hh * sBh;
    unsigned* Cu = Cp + bb * sCb + hh * sCh;

    int m0   = blockIdx.y << 7;
    int tid  = threadIdx.x;
    int lane = tid & 31;
    int wid  = tid >> 5;
    int wm   = wid << 4;

    int K_eff = m0 + 128;           // causal clamp
    if (K_eff > K) K_eff = K;
    const int nk = K_eff >> 4;

    float acc[8][4];
    #pragma unroll
    for (int b = 0; b < 8; b++)
        #pragma unroll
        for (int j = 0; j < 4; j++) acc[b][j] = 0.f;

    const int la_m  = tid >> 2;             // 0..63 (+64 for j=1)
    const int la_k  = (tid & 3) << 2;       // 0,4,8,12
    const int lb_k2 = tid >> 5;             // 0..7
    const int lb_n  = (tid & 31) << 1;      // 0..62

    float4 ra[2]; uint2 rb0, rb1;

    auto LOAD = [&](int k0) {
        #pragma unroll
        for (int j = 0; j < 2; j++) {
            int m = la_m + (j << 6);
            ra[j] = *(const float4*)(A + (size_t)(m0 + m) * lda + (k0 + la_k));
        }
        rb0 = *(const uint2*)(Bp + (size_t)(k0 + 2*lb_k2)     * ldb + lb_n);
        rb1 = *(const uint2*)(Bp + (size_t)(k0 + 2*lb_k2 + 1) * ldb + lb_n);
    };

    auto STORE = [&](int s) {
        uint2* As = smbuf + s * STG2;
        uint2* Bs = As + K2T * P2;
        int k2 = la_k >> 1;
        #pragma unroll
        for (int j = 0; j < 2; j++) {
            int m = la_m + (j << 6);
            unsigned u0 = splitbf(ra[j].x), u1 = splitbf(ra[j].y);
            unsigned u2 = splitbf(ra[j].z), u3 = splitbf(ra[j].w);
            As[(k2    ) * P2 + m] = make_uint2(HIPAIR(u0, u1), LOPAIR(u0, u1));
            As[(k2 + 1) * P2 + m] = make_uint2(HIPAIR(u2, u3), LOPAIR(u2, u3));
        }
        Bs[lb_k2 * P2 + lb_n    ] = make_uint2(HIPAIR(rb0.x, rb1.x), LOPAIR(rb0.x, rb1.x));
        Bs[lb_k2 * P2 + lb_n + 1] = make_uint2(HIPAIR(rb0.y, rb1.y), LOPAIR(rb0.y, rb1.y));
    };

    LOAD(0);
    STORE(0);
    __syncthreads();

    for (int t = 0; t < nk; t++) {
        if (t + 1 < nk) LOAD((t + 1) << 4);

        const uint2* As = smbuf + (t & 1) * STG2;
        const uint2* Bs = As + K2T * P2;

        int k2q = lane & 3;
        int qd  = lane >> 2;
        int r   = wm + qd;
        uint2 a0 = As[ k2q      * P2 + r];
        uint2 a1 = As[ k2q      * P2 + r + 8];
        uint2 a2 = As[(k2q + 4) * P2 + r];
        uint2 a3 = As[(k2q + 4) * P2 + r + 8];
        unsigned ah[4] = {a0.x, a1.x, a2.x, a3.x};
        unsigned al[4] = {a0.y, a1.y, a2.y, a3.y};
        #pragma unroll
        for (int nt = 0; nt < 8; nt++) {
            int cn = (nt << 3) + qd;
            uint2 b0 = Bs[ k2q      * P2 + cn];
            uint2 b1 = Bs[(k2q + 4) * P2 + cn];
            mma_bf16(acc[nt], ah, b0.x, b1.x);
            mma_bf16(acc[nt], ah, b0.y, b1.y);
            mma_bf16(acc[nt], al, b0.x, b1.x);
        }

        if (t + 1 < nk) STORE((t + 1) & 1);
        __syncthreads();
    }

    #pragma unroll
    for (int nt = 0; nt < 8; nt++) {
        int row = m0 + wm + (lane >> 2);
        int col = (nt << 3) + ((lane & 3) << 1);
        #pragma unroll
        for (int j = 0; j < 4; j++) {
            int r = row + ((j & 2) ? 8 : 0);
            int c = col + (j & 1);
            if (c < N)
                Cu[(size_t)r * ldc + c] = splitbf(acc[nt][j]);
        }
    }
}

// ---------------------------------------------------------------------------
// Elementwise split (batched over all layers)
// ---------------------------------------------------------------------------
__global__ void split_k(const float* __restrict__ src, unsigned* __restrict__ dst, int n4)
{
    int i = blockIdx.x * 256 + threadIdx.x;
    if (i < n4) {
        float4 v = ((const float4*)src)[i];
        uint4 o;
        o.x = splitbf(v.x); o.y = splitbf(v.y);
        o.z = splitbf(v.z); o.w = splitbf(v.w);
        ((uint4*)dst)[i] = o;
    }
}

// Pack Wq/Wk/Wv [L,C,C] into split Wcat [L][C][3C], all layers at once.
__global__ void pack_qkv_split(const float* __restrict__ Wq, const float* __restrict__ Wk,
                               const float* __restrict__ Wv, unsigned* __restrict__ Wcat)
{
    int i = blockIdx.x * 256 + threadIdx.x;
    if (i < L_ * C_ * C_) {
        int l = i / (C_ * C_);
        int r = i - l * (C_ * C_);
        int k = r / C_, j = r - k * C_;
        unsigned* W = Wcat + (size_t)l * C_ * C3_;
        W[(size_t)k * C3_ + j]          = splitbf(Wq[i]);
        W[(size_t)k * C3_ + C_ + j]     = splitbf(Wk[i]);
        W[(size_t)k * C3_ + 2 * C_ + j] = splitbf(Wv[i]);
    }
}

// ---------------------------------------------------------------------------
// LayerNorm (biased variance, eps=1e-5) -> split u32 output
// ---------------------------------------------------------------------------
__global__ void layernorm_split(const float* __restrict__ x, const float* __restrict__ g,
                                const float* __restrict__ b, unsigned* __restrict__ y)
{
    int row = blockIdx.x;
    const float* xr = x + (size_t)row * C_;
    unsigned* yr    = y + (size_t)row * C_;
    int tid = threadIdx.x;
    float s = 0.f, s2 = 0.f;
    for (int c = tid; c < C_; c += 256) { float v = xr[c]; s += v; s2 += v * v; }
    __shared__ float shs[8], shs2[8];
    #pragma unroll
    for (int o = 16; o; o >>= 1) {
        s  += __shfl_xor_sync(0xffffffffu, s,  o);
        s2 += __shfl_xor_sync(0xffffffffu, s2, o);
    }
    if ((tid & 31) == 0) { shs[tid >> 5] = s; shs2[tid >> 5] = s2; }
    __syncthreads();
    float ts = 0.f, ts2 = 0.f;
    #pragma unroll
    for (int i = 0; i < 8; i++) { ts += shs[i]; ts2 += shs2[i]; }
    float mean = ts * (1.f / C_);
    float var  = ts2 * (1.f / C_) - mean * mean;
    float rstd = rsqrtf(var + 1e-5f);
    for (int c = tid; c < C_; c += 256)
        yr[c] = splitbf((xr[c] - mean) * rstd * g[c] + b[c]);
}

// ---------------------------------------------------------------------------
// Causal softmax in place; reads valid prefix, writes to next 128 boundary.
// ---------------------------------------------------------------------------
__global__ void softmax_causal(float* __restrict__ att)
{
    int row = blockIdx.x;             // b*H*T + h*T + q
    int q   = row & (T_ - 1);
    float* a = att + (size_t)row * T_;
    int len  = q + 1;
    int wlim = ((q >> 7) + 1) << 7;
    int tid  = threadIdx.x;
    __shared__ float sh[8];

    float r[4];
    #pragma unroll
    for (int i = 0; i < 4; i++) {
        int c = tid + (i << 8);
        r[i] = (c < len) ? a[c] : -3.0e38f;
    }
    float mx = fmaxf(fmaxf(r[0], r[1]), fmaxf(r[2], r[3]));
    #pragma unroll
    for (int o = 16; o; o >>= 1) mx = fmaxf(mx, __shfl_xor_sync(0xffffffffu, mx, o));
    if ((tid & 31) == 0) sh[tid >> 5] = mx;
    __syncthreads();
    mx = sh[0];
    #pragma unroll
    for (int i = 1; i < 8; i++) mx = fmaxf(mx, sh[i]);
    __syncthreads();

    float s = 0.f;
    #pragma unroll
    for (int i = 0; i < 4; i++) {
        int c = tid + (i << 8);
        r[i] = (c < len) ? expf(r[i] - mx) : 0.f;
        s += r[i];
    }
    #pragma unroll
    for (int o = 16; o; o >>= 1) s += __shfl_xor_sync(0xffffffffu, s, o);
    if ((tid & 31) == 0) sh[tid >> 5] = s;
    __syncthreads();
    float tot = 0.f;
    #pragma unroll
    for (int i = 0; i < 8; i++) tot += sh[i];
    float inv = 1.f / tot;

    #pragma unroll
    for (int i = 0; i < 4; i++) {
        int c = tid + (i << 8);
        if (c < wlim) a[c] = r[i] * inv;
    }
}

// ---------------------------------------------------------------------------
// Embedding
// ---------------------------------------------------------------------------
__global__ void embed_k(const int* __restrict__ idx, const float* __restrict__ tok,
                        const float* __restrict__ pos, float* __restrict__ x)
{
    int r = blockIdx.x;
    int t = r & (T_ - 1);
    int token = idx[r];
    const float* te = tok + (size_t)token * C_;
    const float* pe = pos + (size_t)t * C_;
    float* xr = x + (size_t)r * C_;
    for (int c = threadIdx.x; c < C_; c += 256) xr[c] = te[c] + pe[c];
}

// ---------------------------------------------------------------------------
// Launch
// ---------------------------------------------------------------------------
extern "C" void kernel_launch(void* const* d_in, const int* in_sizes, int n_in,
                              void* d_out, int out_size)
{
    (void)in_sizes; (void)n_in; (void)out_size;
    const int*   idx = (const int*)d_in[0];
    const float* tok = (const float*)d_in[1];
    const float* pos = (const float*)d_in[2];
    const float* Wq  = (const float*)d_in[3];
    const float* Wk  = (const float*)d_in[4];
    const float* Wv  = (const float*)d_in[5];
    const float* Wp  = (const float*)d_in[6];
    const float* bp  = (const float*)d_in[7];
    const float* g1  = (const float*)d_in[8];
    const float* be1 = (const float*)d_in[9];
    const float* g2  = (const float*)d_in[10];
    const float* be2 = (const float*)d_in[11];
    const float* W1  = (const float*)d_in[12];
    const float* bb1 = (const float*)d_in[13];
    const float* W2  = (const float*)d_in[14];
    const float* bb2 = (const float*)d_in[15];
    const float* gf  = (const float*)d_in[16];
    const float* bf  = (const float*)d_in[17];
    const float* Wh  = (const float*)d_in[18];
    const float* bhd = (const float*)d_in[19];
    float* out = (float*)d_out;

    float    *x, *att;
    unsigned *h2, *qkv2, *o2, *a12, *wcat2, *wp2, *w12, *w22, *wh2;
    cudaGetSymbolAddress((void**)&x,     g_x);
    cudaGetSymbolAddress((void**)&h2,    g_h2);
    cudaGetSymbolAddress((void**)&qkv2,  g_qkv2);
    cudaGetSymbolAddress((void**)&o2,    g_o2);
    cudaGetSymbolAddress((void**)&a12,   g_a12);
    cudaGetSymbolAddress((void**)&att,   g_att);
    cudaGetSymbolAddress((void**)&wcat2, g_wcat2);
    cudaGetSymbolAddress((void**)&wp2,   g_wp2);
    cudaGetSymbolAddress((void**)&w12,   g_w12);
    cudaGetSymbolAddress((void**)&w22,   g_w22);
    cudaGetSymbolAddress((void**)&wh2,   g_wh2);

    const float att_scale = 0.03608439182435161f;  // 768^-0.5 (reference uses full C)
    const float* NOF = (const float*)0;

    embed_k<<<BT_, 256>>>(idx, tok, pos, x);

    // --- pre-split all weights (batched over layers) ---
    pack_qkv_split<<<(L_ * C_ * C_ + 255) / 256, 256>>>(Wq, Wk, Wv, wcat2);
    split_k<<<(L_ * C_ * C_  / 4 + 255) / 256, 256>>>(Wp, wp2, L_ * C_ * C_  / 4);
    split_k<<<(L_ * C_ * C4_ / 4 + 255) / 256, 256>>>(W1, w12, L_ * C_ * C4_ / 4);
    split_k<<<(L_ * C4_ * C_ / 4 + 255) / 256, 256>>>(W2, w22, L_ * C4_ * C_ / 4);
    split_k<<<(C_ * V_ / 4 + 255) / 256, 256>>>(Wh, wh2, C_ * V_ / 4);

    dim3 gqkv(C3_ / 128, BT_ / 128, 1);
    dim3 gcc (C_  / 128, BT_ / 128, 1);
    dim3 gsc (T_  / 128, T_  / 128, B_ * H_);
    dim3 gav (1,         T_  / 128, B_ * H_);
    dim3 gf1 (C4_ / 128, BT_ / 128, 1);

    for (int l = 0; l < L_; l++) {
        layernorm_split<<<BT_, 256>>>(x, g1 + l * C_, be1 + l * C_, h2);

        // qkv = h @ Wcat -> split [BT, 3C]
        gemmb<<<gqkv, 512, SMEM_BYTES>>>(h2, wcat2 + (size_t)l * C_ * C3_, (float*)qkv2,
                BT_, C3_, C_, C_, C3_, C3_,
                0, 0, 0, 0, 0, 0, 1, NOF, NOF, 1.f, 0, 0, 1, 0);

        // scores: Q @ K^T per (b,h) -> plain att, upper blocks skipped
        gemmb<<<gsc, 512, SMEM_BYTES>>>(qkv2, qkv2 + C_, att,
                T_, T_, HS_, C3_, C3_, T_,
                (long long)T_ * C3_, (long long)HS_,
                (long long)T_ * C3_, (long long)HS_,
                (long long)H_ * T_ * T_, (long long)T_ * T_, H_,
                NOF, NOF, att_scale, 0, 1, 0, 1);

        softmax_causal<<<B_ * H_ * T_, 256>>>(att);

        // AV: P @ V -> split o (causally clamped K)
        gemm_av<<<gav, 256, SMEM_BYTES>>>(att, qkv2 + 2 * C_, o2,
                T_, T_, C3_, C_,
                (long long)H_ * T_ * T_, (long long)T_ * T_,
                (long long)T_ * C3_, (long long)HS_,
                (long long)T_ * C_, (long long)HS_, H_);

        // x = x + o @ Wproj + bproj (plain out)
        gemmb<<<gcc, 512, SMEM_BYTES>>>(o2, wp2 + (size_t)l * C_ * C_, x,
                BT_, C_, C_, C_, C_, C_,
                0, 0, 0, 0, 0, 0, 1, bp + l * C_, x, 1.f, 0, 0, 0, 0);

        layernorm_split<<<BT_, 256>>>(x, g2 + l * C_, be2 + l * C_, h2);

        // a1 = gelu(h @ W1 + b1) -> split
        gemmb<<<gf1, 512, SMEM_BYTES>>>(h2, w12 + (size_t)l * C_ * C4_, (float*)a12,
                BT_, C4_, C_, C_, C4_, C4_,
                0, 0, 0, 0, 0, 0, 1, bb1 + l * C4_, NOF, 1.f, 1, 0, 1, 0);

        // x = x + a1 @ W2 + b2 (plain out)
        gemmb<<<gcc, 512, SMEM_BYTES>>>(a12, w22 + (size_t)l * C4_ * C_, x,
                BT_, C_, C4_, C4_, C_, C_,
                0, 0, 0, 0, 0, 0, 1, bb2 + l * C_, x, 1.f, 0, 0, 0, 0);
    }

    layernorm_split<<<BT_, 256>>>(x, gf, bf, h2);

    // head: 3-term bf16 (2-term bf16 would be ~2e-3 — insufficient)
    dim3 ghd(V_ / 128, BT_ / 128, 1);
    gemmb<<<ghd, 512, SMEM_BYTES>>>(h2, wh2, out,
            BT_, V_, C_, C_, V_, V_,
            0, 0, 0, 0, 0, 0, 1, bhd, NOF, 1.f, 0, 0, 0, 0);
}

// round 13
// speedup vs baseline: 2.2006x; 1.1659x over previous
#include <cuda_runtime.h>
#include <cuda_bf16.h>
#include <math.h>

// ---------------------------------------------------------------------------
// GPT-2 small forward. fp32 activations; GEMMs use split-bf16 (3xBF16)
// mma.sync.m16n8k16. ALL operands are pre-split AND pre-packed into k-pair
// planar uint2 {hi16x2, lo16x2} by producers (split kernels, layernorm,
// softmax, GEMM epilogues), so every GEMM hot path is pure LDG/STS/LDS/MMA.
// 512-thread CTAs, KT=16 double-buffered, causal-aware attention.
// ---------------------------------------------------------------------------

namespace {
constexpr int B_  = 4;
constexpr int T_  = 1024;
constexpr int C_  = 768;
constexpr int H_  = 12;
constexpr int HS_ = 64;
constexpr int L_  = 12;
constexpr int V_  = 32000;
constexpr int BT_ = B_ * T_;
constexpr int C4_ = 4 * C_;
constexpr int C3_ = 3 * C_;

constexpr int KT  = 16;                 // k per tile
constexpr int K2T = KT / 2;             // k-pairs per tile (8)
constexpr int P2  = 132;                // smem row pitch in uint2
constexpr int STG2 = 2 * K2T * P2;      // uint2 per stage (As + Bs)
constexpr size_t SMEM_BYTES = 2 * STG2 * sizeof(uint2);   // 33792 B
}

// Scratch (no cudaMalloc -> device globals)
__device__ float    g_x   [BT_ * C_];
__device__ uint2    g_h2  [BT_ * C_ / 2];      // PP: [row][C/2]
__device__ unsigned g_qkv2[BT_ * C3_];         // EW u32 per element
__device__ uint2    g_o2  [BT_ * C_ / 2];      // PP
__device__ uint2    g_a12 [BT_ * C4_ / 2];     // PP
__device__ float    g_att [(size_t)B_ * H_ * T_ * T_];   // float, then PP in place
// all-layer pre-split packed weights: [k2][n] uint2
__device__ uint2 g_wcat2[(size_t)L_ * (C_ / 2) * C3_];
__device__ uint2 g_wp2  [(size_t)L_ * (C_ / 2) * C_];
__device__ uint2 g_w12  [(size_t)L_ * (C_ / 2) * C4_];
__device__ uint2 g_w22  [(size_t)L_ * (C4_ / 2) * C_];
__device__ uint2 g_wh2  [(size_t)(C_ / 2) * V_];

// ---------------------------------------------------------------------------
// bf16 split helpers
// ---------------------------------------------------------------------------
__device__ __forceinline__ unsigned splitbf(float x) {
    __nv_bfloat16 h = __float2bfloat16(x);
    float hf = __bfloat162float(h);
    __nv_bfloat16 l = __float2bfloat16(x - hf);
    return (unsigned)__bfloat16_as_ushort(h) |
           ((unsigned)__bfloat16_as_ushort(l) << 16);
}

#define HIPAIR(e0, e1) __byte_perm((e0), (e1), 0x5410)
#define LOPAIR(e0, e1) __byte_perm((e0), (e1), 0x7632)

__device__ __forceinline__ uint2 packpair(float a, float b) {
    unsigned u0 = splitbf(a), u1 = splitbf(b);
    return make_uint2(HIPAIR(u0, u1), LOPAIR(u0, u1));
}

__device__ __forceinline__ void mma_bf16(float* d, const unsigned* a,
                                         unsigned b0, unsigned b1) {
    asm volatile(
        "mma.sync.aligned.m16n8k16.row.col.f32.bf16.bf16.f32 "
        "{%0,%1,%2,%3}, {%4,%5,%6,%7}, {%8,%9}, {%0,%1,%2,%3};"
        : "+f"(d[0]), "+f"(d[1]), "+f"(d[2]), "+f"(d[3])
        : "r"(a[0]), "r"(a[1]), "r"(a[2]), "r"(a[3]),
          "r"(b0), "r"(b1));
}

// ---------------------------------------------------------------------------
// Linear GEMM: C = A@B (+bias)(+gelu)(+resid). A: PP [M][K/2] uint2.
// B: PP [K/2][N] uint2. 512 threads, tile 128x128x16, 16 warps (4x4),
// warp tile 32x32. outMode: 0 plain float, 1 EW u32, 2 PP uint2.
// M%128==0, N%128==0, K%16==0. Hot path: LDG.128 -> STS -> LDS.64 -> MMA.
// ---------------------------------------------------------------------------
__global__ void __launch_bounds__(512)
gemm_lin(const uint2* __restrict__ A, const uint2* __restrict__ Bw,
         float* __restrict__ Cp, int M, int N, int K,
         const float* __restrict__ bias, const float* __restrict__ resid,
         int doGelu, int outMode)
{
    extern __shared__ uint2 smbuf[];
    const int ldaH = K >> 1;            // uint2 per A row

    int m0   = blockIdx.y << 7;
    int n0   = blockIdx.x << 7;
    int tid  = threadIdx.x;
    int lane = tid & 31;
    int wid  = tid >> 5;
    int wm   = (wid & 3) << 5;
    int wn   = (wid >> 2) << 5;

    float acc[2][4][4];
    #pragma unroll
    for (int a = 0; a < 2; a++)
        #pragma unroll
        for (int b = 0; b < 4; b++)
            #pragma unroll
            for (int j = 0; j < 4; j++) acc[a][b][j] = 0.f;

    const int la_m  = tid >> 2;             // 0..127
    const int la_k2 = (tid & 3) << 1;       // 0,2,4,6 (uint4 = k2,k2+1)
    const int lb_k2 = tid >> 6;             // 0..7
    const int lb_n  = (tid & 63) << 1;      // 0..126

    uint4 ra, rb;
    const int nk = K >> 4;

    auto LOAD = [&](int kh) {   // kh = k-pair base of tile
        ra = *(const uint4*)(A  + (size_t)(m0 + la_m) * ldaH + (kh + la_k2));
        rb = *(const uint4*)(Bw + (size_t)(kh + lb_k2) * N + (n0 + lb_n));
    };
    auto STORE = [&](int s) {
        uint2* As = smbuf + s * STG2;
        uint2* Bs = As + K2T * P2;
        As[(la_k2    ) * P2 + la_m] = make_uint2(ra.x, ra.y);
        As[(la_k2 + 1) * P2 + la_m] = make_uint2(ra.z, ra.w);
        *(uint4*)&Bs[lb_k2 * P2 + lb_n] = rb;
    };

    LOAD(0);
    STORE(0);
    __syncthreads();

    for (int t = 0; t < nk; t++) {
        if (t + 1 < nk) LOAD((t + 1) << 3);

        const uint2* As = smbuf + (t & 1) * STG2;
        const uint2* Bs = As + K2T * P2;

        int k2q = lane & 3;
        int qd  = lane >> 2;
        uint2 aA[2][4];
        #pragma unroll
        for (int mt = 0; mt < 2; mt++) {
            int r = wm + (mt << 4) + qd;
            aA[mt][0] = As[ k2q      * P2 + r];
            aA[mt][1] = As[ k2q      * P2 + r + 8];
            aA[mt][2] = As[(k2q + 4) * P2 + r];
            aA[mt][3] = As[(k2q + 4) * P2 + r + 8];
        }
        uint2 bB[4][2];
        #pragma unroll
        for (int nt = 0; nt < 4; nt++) {
            int cn = wn + (nt << 3) + qd;
            bB[nt][0] = Bs[ k2q      * P2 + cn];
            bB[nt][1] = Bs[(k2q + 4) * P2 + cn];
        }
        #pragma unroll
        for (int mt = 0; mt < 2; mt++) {
            unsigned ah[4] = {aA[mt][0].x, aA[mt][1].x, aA[mt][2].x, aA[mt][3].x};
            unsigned al[4] = {aA[mt][0].y, aA[mt][1].y, aA[mt][2].y, aA[mt][3].y};
            #pragma unroll
            for (int nt = 0; nt < 4; nt++) {
                mma_bf16(acc[mt][nt], ah, bB[nt][0].x, bB[nt][1].x);
                mma_bf16(acc[mt][nt], ah, bB[nt][0].y, bB[nt][1].y);
                mma_bf16(acc[mt][nt], al, bB[nt][0].x, bB[nt][1].x);
            }
        }

        if (t + 1 < nk) STORE((t + 1) & 1);
        __syncthreads();
    }

    // ---- epilogue ----
    unsigned* Cu = (unsigned*)Cp;
    uint2*    Cq = (uint2*)Cp;
    #pragma unroll
    for (int mt = 0; mt < 2; mt++) {
        #pragma unroll
        for (int nt = 0; nt < 4; nt++) {
            int row = m0 + wm + (mt << 4) + (lane >> 2);
            int col = n0 + wn + (nt << 3) + ((lane & 3) << 1);
            float v[4];
            #pragma unroll
            for (int j = 0; j < 4; j++) {
                int r = row + ((j & 2) ? 8 : 0);
                int c = col + (j & 1);
                float vv = acc[mt][nt][j];
                if (bias) vv += bias[c];
                if (doGelu) vv = 0.5f * vv * (1.f + erff(vv * 0.70710678118654752f));
                if (resid) vv += resid[(size_t)r * N + c];
                v[j] = vv;
            }
            if (outMode == 0) {
                *(float2*)&Cp[(size_t)row * N + col]       = make_float2(v[0], v[1]);
                *(float2*)&Cp[(size_t)(row + 8) * N + col] = make_float2(v[2], v[3]);
            } else if (outMode == 1) {
                Cu[(size_t)row * N + col]           = splitbf(v[0]);
                Cu[(size_t)row * N + col + 1]       = splitbf(v[1]);
                Cu[(size_t)(row + 8) * N + col]     = splitbf(v[2]);
                Cu[(size_t)(row + 8) * N + col + 1] = splitbf(v[3]);
            } else {
                Cq[(size_t)row * (N >> 1) + (col >> 1)]       = packpair(v[0], v[1]);
                Cq[(size_t)(row + 8) * (N >> 1) + (col >> 1)] = packpair(v[2], v[3]);
            }
        }
    }
}

// ---------------------------------------------------------------------------
// Scores GEMM: att[b,h] = Q @ K^T * alpha. A,B elementwise u32 in qkv2
// (rows strided C3). 512 threads, tile 128x128, K=HS=64. Upper-triangular
// blocks skipped. Output plain float.
// ---------------------------------------------------------------------------
__global__ void __launch_bounds__(512)
gemm_sc(const unsigned* __restrict__ qkv, float* __restrict__ att, float alpha)
{
    if (blockIdx.x > blockIdx.y) return;
    extern __shared__ uint2 smbuf[];

    int bz = blockIdx.z;
    const unsigned* A  = qkv + (size_t)(bz / H_) * T_ * C3_ + (size_t)(bz % H_) * HS_;
    const unsigned* Bq = A + C_;
    float* Cb = att + (size_t)bz * T_ * T_;

    int m0   = blockIdx.y << 7;
    int n0   = blockIdx.x << 7;
    int tid  = threadIdx.x;
    int lane = tid & 31;
    int wid  = tid >> 5;
    int wm   = (wid & 3) << 5;
    int wn   = (wid >> 2) << 5;

    float acc[2][4][4];
    #pragma unroll
    for (int a = 0; a < 2; a++)
        #pragma unroll
        for (int b = 0; b < 4; b++)
            #pragma unroll
            for (int j = 0; j < 4; j++) acc[a][b][j] = 0.f;

    const int la_m = tid >> 2;              // 0..127
    const int la_k = (tid & 3) << 2;        // 0,4,8,12

    uint4 ra, rbT;
    const int nk = HS_ >> 4;                // 4

    auto LOAD = [&](int k0) {
        ra  = *(const uint4*)(A  + (size_t)(m0 + la_m) * C3_ + (k0 + la_k));
        rbT = *(const uint4*)(Bq + (size_t)(n0 + la_m) * C3_ + (k0 + la_k));
    };
    auto STORE = [&](int s) {
        uint2* As = smbuf + s * STG2;
        uint2* Bs = As + K2T * P2;
        int k2 = la_k >> 1;
        As[(k2    ) * P2 + la_m] = make_uint2(HIPAIR(ra.x, ra.y), LOPAIR(ra.x, ra.y));
        As[(k2 + 1) * P2 + la_m] = make_uint2(HIPAIR(ra.z, ra.w), LOPAIR(ra.z, ra.w));
        Bs[(k2    ) * P2 + la_m] = make_uint2(HIPAIR(rbT.x, rbT.y), LOPAIR(rbT.x, rbT.y));
        Bs[(k2 + 1) * P2 + la_m] = make_uint2(HIPAIR(rbT.z, rbT.w), LOPAIR(rbT.z, rbT.w));
    };

    LOAD(0);
    STORE(0);
    __syncthreads();

    for (int t = 0; t < nk; t++) {
        if (t + 1 < nk) LOAD((t + 1) << 4);

        const uint2* As = smbuf + (t & 1) * STG2;
        const uint2* Bs = As + K2T * P2;

        int k2q = lane & 3;
        int qd  = lane >> 2;
        uint2 aA[2][4];
        #pragma unroll
        for (int mt = 0; mt < 2; mt++) {
            int r = wm + (mt << 4) + qd;
            aA[mt][0] = As[ k2q      * P2 + r];
            aA[mt][1] = As[ k2q      * P2 + r + 8];
            aA[mt][2] = As[(k2q + 4) * P2 + r];
            aA[mt][3] = As[(k2q + 4) * P2 + r + 8];
        }
        uint2 bB[4][2];
        #pragma unroll
        for (int nt = 0; nt < 4; nt++) {
            int cn = wn + (nt << 3) + qd;
            bB[nt][0] = Bs[ k2q      * P2 + cn];
            bB[nt][1] = Bs[(k2q + 4) * P2 + cn];
        }
        #pragma unroll
        for (int mt = 0; mt < 2; mt++) {
            unsigned ah[4] = {aA[mt][0].x, aA[mt][1].x, aA[mt][2].x, aA[mt][3].x};
            unsigned al[4] = {aA[mt][0].y, aA[mt][1].y, aA[mt][2].y, aA[mt][3].y};
            #pragma unroll
            for (int nt = 0; nt < 4; nt++) {
                mma_bf16(acc[mt][nt], ah, bB[nt][0].x, bB[nt][1].x);
                mma_bf16(acc[mt][nt], ah, bB[nt][0].y, bB[nt][1].y);
                mma_bf16(acc[mt][nt], al, bB[nt][0].x, bB[nt][1].x);
            }
        }

        if (t + 1 < nk) STORE((t + 1) & 1);
        __syncthreads();
    }

    #pragma unroll
    for (int mt = 0; mt < 2; mt++) {
        #pragma unroll
        for (int nt = 0; nt < 4; nt++) {
            int row = m0 + wm + (mt << 4) + (lane >> 2);
            int col = n0 + wn + (nt << 3) + ((lane & 3) << 1);
            *(float2*)&Cb[(size_t)row * T_ + col] =
                make_float2(acc[mt][nt][0] * alpha, acc[mt][nt][1] * alpha);
            *(float2*)&Cb[(size_t)(row + 8) * T_ + col] =
                make_float2(acc[mt][nt][2] * alpha, acc[mt][nt][3] * alpha);
        }
    }
}

// ---------------------------------------------------------------------------
// AV GEMM: o[b,h] = P @ V. A = att, PRE-SPLIT-PACKED in place by softmax
// ([row][T/2] uint2). B = V elementwise u32 (PRMT-packed in staging).
// 256 threads, 8 warps x 1, warp tile 16x64. K causally clamped. Out PP.
// ---------------------------------------------------------------------------
__global__ void __launch_bounds__(256)
gemm_av(const float* __restrict__ attf, const unsigned* __restrict__ qkv,
        uint2* __restrict__ o2)
{
    extern __shared__ uint2 smbuf[];
    int bz = blockIdx.z;
    const uint2* Apk = (const uint2*)attf + (size_t)bz * T_ * (T_ / 2);
    const unsigned* Bp = qkv + (size_t)(bz / H_) * T_ * C3_ + (size_t)(bz % H_) * HS_ + 2 * C_;
    uint2* Cq = o2 + (size_t)(bz / H_) * T_ * (C_ / 2) + (size_t)(bz % H_) * (HS_ / 2);

    int m0   = blockIdx.y << 7;
    int tid  = threadIdx.x;
    int lane = tid & 31;
    int wid  = tid >> 5;
    int wm   = wid << 4;

    const int nk = (m0 + 128) >> 4;     // causal clamp (K = T)

    float acc[8][4];
    #pragma unroll
    for (int b = 0; b < 8; b++)
        #pragma unroll
        for (int j = 0; j < 4; j++) acc[b][j] = 0.f;

    const int la_m  = tid >> 2;             // 0..63 (+64 for j=1)
    const int la_k2 = (tid & 3) << 1;       // 0,2,4,6
    const int lb_k2 = tid >> 5;             // 0..7
    const int lb_n  = (tid & 31) << 1;      // 0..62

    uint4 ra[2]; uint2 rb0, rb1;

    auto LOAD = [&](int kh) {
        #pragma unroll
        for (int j = 0; j < 2; j++) {
            int m = la_m + (j << 6);
            ra[j] = *(const uint4*)(Apk + (size_t)(m0 + m) * (T_ / 2) + (kh + la_k2));
        }
        int k0 = kh << 1;
        rb0 = *(const uint2*)(Bp + (size_t)(k0 + 2 * lb_k2)     * C3_ + lb_n);
        rb1 = *(const uint2*)(Bp + (size_t)(k0 + 2 * lb_k2 + 1) * C3_ + lb_n);
    };
    auto STORE = [&](int s) {
        uint2* As = smbuf + s * STG2;
        uint2* Bs = As + K2T * P2;
        #pragma unroll
        for (int j = 0; j < 2; j++) {
            int m = la_m + (j << 6);
            As[(la_k2    ) * P2 + m] = make_uint2(ra[j].x, ra[j].y);
            As[(la_k2 + 1) * P2 + m] = make_uint2(ra[j].z, ra[j].w);
        }
        Bs[lb_k2 * P2 + lb_n    ] = make_uint2(HIPAIR(rb0.x, rb1.x), LOPAIR(rb0.x, rb1.x));
        Bs[lb_k2 * P2 + lb_n + 1] = make_uint2(HIPAIR(rb0.y, rb1.y), LOPAIR(rb0.y, rb1.y));
    };

    LOAD(0);
    STORE(0);
    __syncthreads();

    for (int t = 0; t < nk; t++) {
        if (t + 1 < nk) LOAD((t + 1) << 3);

        const uint2* As = smbuf + (t & 1) * STG2;
        const uint2* Bs = As + K2T * P2;

        int k2q = lane & 3;
        int qd  = lane >> 2;
        int r   = wm + qd;
        uint2 a0 = As[ k2q      * P2 + r];
        uint2 a1 = As[ k2q      * P2 + r + 8];
        uint2 a2 = As[(k2q + 4) * P2 + r];
        uint2 a3 = As[(k2q + 4) * P2 + r + 8];
        unsigned ah[4] = {a0.x, a1.x, a2.x, a3.x};
        unsigned al[4] = {a0.y, a1.y, a2.y, a3.y};
        #pragma unroll
        for (int nt = 0; nt < 8; nt++) {
            int cn = (nt << 3) + qd;
            uint2 b0 = Bs[ k2q      * P2 + cn];
            uint2 b1 = Bs[(k2q + 4) * P2 + cn];
            mma_bf16(acc[nt], ah, b0.x, b1.x);
            mma_bf16(acc[nt], ah, b0.y, b1.y);
            mma_bf16(acc[nt], al, b0.x, b1.x);
        }

        if (t + 1 < nk) STORE((t + 1) & 1);
        __syncthreads();
    }

    #pragma unroll
    for (int nt = 0; nt < 8; nt++) {
        int row = m0 + wm + (lane >> 2);
        int col = (nt << 3) + ((lane & 3) << 1);
        Cq[(size_t)row * (C_ / 2) + (col >> 1)]       = packpair(acc[nt][0], acc[nt][1]);
        Cq[(size_t)(row + 8) * (C_ / 2) + (col >> 1)] = packpair(acc[nt][2], acc[nt][3]);
    }
}

// ---------------------------------------------------------------------------
// Weight pre-pack: src rows paired -> PP [rows/2][N] uint2
// ---------------------------------------------------------------------------
__global__ void pack_w(const float* __restrict__ src, uint2* __restrict__ dst,
                       int halfRows, int N)
{
    int i = blockIdx.x * 256 + threadIdx.x;
    if (i < halfRows * N) {
        int g = i / N, j = i - g * N;
        dst[i] = packpair(src[(size_t)(2 * g) * N + j],
                          src[(size_t)(2 * g + 1) * N + j]);
    }
}

// Pack Wq/Wk/Wv [L][C][C] -> PP Wcat [L][C/2][3C]
__global__ void pack_qkv_pp(const float* __restrict__ Wq, const float* __restrict__ Wk,
                            const float* __restrict__ Wv, uint2* __restrict__ Wcat)
{
    int i = blockIdx.x * 256 + threadIdx.x;
    if (i < L_ * (C_ / 2) * C_) {
        int l  = i / ((C_ / 2) * C_);
        int rm = i - l * ((C_ / 2) * C_);
        int k2 = rm / C_, j = rm - k2 * C_;
        size_t so = (size_t)l * C_ * C_;
        uint2* W = Wcat + (size_t)l * (C_ / 2) * C3_ + (size_t)k2 * C3_;
        W[j]            = packpair(Wq[so + (size_t)(2*k2) * C_ + j], Wq[so + (size_t)(2*k2+1) * C_ + j]);
        W[C_ + j]       = packpair(Wk[so + (size_t)(2*k2) * C_ + j], Wk[so + (size_t)(2*k2+1) * C_ + j]);
        W[2 * C_ + j]   = packpair(Wv[so + (size_t)(2*k2) * C_ + j], Wv[so + (size_t)(2*k2+1) * C_ + j]);
    }
}

// ---------------------------------------------------------------------------
// LayerNorm (biased variance, eps=1e-5) -> PP uint2 output
// ---------------------------------------------------------------------------
__global__ void layernorm_pp(const float* __restrict__ x, const float* __restrict__ g,
                             const float* __restrict__ b, uint2* __restrict__ y)
{
    int row = blockIdx.x;
    const float* xr = x + (size_t)row * C_;
    uint2* yr       = y + (size_t)row * (C_ / 2);
    int tid = threadIdx.x;
    float s = 0.f, s2 = 0.f;
    for (int c = tid; c < C_; c += 256) { float v = xr[c]; s += v; s2 += v * v; }
    __shared__ float shs[8], shs2[8];
    #pragma unroll
    for (int o = 16; o; o >>= 1) {
        s  += __shfl_xor_sync(0xffffffffu, s,  o);
        s2 += __shfl_xor_sync(0xffffffffu, s2, o);
    }
    if ((tid & 31) == 0) { shs[tid >> 5] = s; shs2[tid >> 5] = s2; }
    __syncthreads();
    float ts = 0.f, ts2 = 0.f;
    #pragma unroll
    for (int i = 0; i < 8; i++) { ts += shs[i]; ts2 += shs2[i]; }
    float mean = ts * (1.f / C_);
    float var  = ts2 * (1.f / C_) - mean * mean;
    float rstd = rsqrtf(var + 1e-5f);
    for (int p = tid; p < C_ / 2; p += 256) {
        float2 xv = ((const float2*)xr)[p];
        float2 gv = ((const float2*)g)[p];
        float2 bv = ((const float2*)b)[p];
        yr[p] = packpair((xv.x - mean) * rstd * gv.x + bv.x,
                         (xv.y - mean) * rstd * gv.y + bv.y);
    }
}

// ---------------------------------------------------------------------------
// Causal softmax: read plain float att row, write SPLIT-PACKED uint2 pairs
// in place (same bytes). Writes only to the next 128 boundary.
// ---------------------------------------------------------------------------
__global__ void softmax_causal(float* __restrict__ att)
{
    int row = blockIdx.x;             // b*H*T + h*T + q
    int q   = row & (T_ - 1);
    float* a = att + (size_t)row * T_;
    uint2* apk = (uint2*)a;
    int len  = q + 1;
    int wlim = ((q >> 7) + 1) << 7;
    int tid  = threadIdx.x;
    __shared__ float sh[8];

    float r[4];
    #pragma unroll
    for (int i = 0; i < 2; i++) {
        int p = tid + (i << 8);
        float2 v = ((const float2*)a)[p];
        r[2*i]     = (2*p     < len) ? v.x : -3.0e38f;
        r[2*i + 1] = (2*p + 1 < len) ? v.y : -3.0e38f;
    }
    float mx = fmaxf(fmaxf(r[0], r[1]), fmaxf(r[2], r[3]));
    #pragma unroll
    for (int o = 16; o; o >>= 1) mx = fmaxf(mx, __shfl_xor_sync(0xffffffffu, mx, o));
    if ((tid & 31) == 0) sh[tid >> 5] = mx;
    __syncthreads();
    mx = sh[0];
    #pragma unroll
    for (int i = 1; i < 8; i++) mx = fmaxf(mx, sh[i]);
    __syncthreads();

    float s = 0.f;
    #pragma unroll
    for (int i = 0; i < 2; i++) {
        int p = tid + (i << 8);
        r[2*i]     = (2*p     < len) ? expf(r[2*i]     - mx) : 0.f;
        r[2*i + 1] = (2*p + 1 < len) ? expf(r[2*i + 1] - mx) : 0.f;
        s += r[2*i] + r[2*i + 1];
    }
    #pragma unroll
    for (int o = 16; o; o >>= 1) s += __shfl_xor_sync(0xffffffffu, s, o);
    if ((tid & 31) == 0) sh[tid >> 5] = s;
    __syncthreads();
    float tot = 0.f;
    #pragma unroll
    for (int i = 0; i < 8; i++) tot += sh[i];
    float inv = 1.f / tot;

    #pragma unroll
    for (int i = 0; i < 2; i++) {
        int p = tid + (i << 8);
        if (2 * p < wlim)
            apk[p] = packpair(r[2*i] * inv, r[2*i + 1] * inv);
    }
}

// ---------------------------------------------------------------------------
// Embedding
// ---------------------------------------------------------------------------
__global__ void embed_k(const int* __restrict__ idx, const float* __restrict__ tok,
                        const float* __restrict__ pos, float* __restrict__ x)
{
    int r = blockIdx.x;
    int t = r & (T_ - 1);
    int token = idx[r];
    const float* te = tok + (size_t)token * C_;
    const float* pe = pos + (size_t)t * C_;
    float* xr = x + (size_t)r * C_;
    for (int c = threadIdx.x; c < C_; c += 256) xr[c] = te[c] + pe[c];
}

// ---------------------------------------------------------------------------
// Launch
// ---------------------------------------------------------------------------
extern "C" void kernel_launch(void* const* d_in, const int* in_sizes, int n_in,
                              void* d_out, int out_size)
{
    (void)in_sizes; (void)n_in; (void)out_size;
    const int*   idx = (const int*)d_in[0];
    const float* tok = (const float*)d_in[1];
    const float* pos = (const float*)d_in[2];
    const float* Wq  = (const float*)d_in[3];
    const float* Wk  = (const float*)d_in[4];
    const float* Wv  = (const float*)d_in[5];
    const float* Wp  = (const float*)d_in[6];
    const float* bp  = (const float*)d_in[7];
    const float* g1  = (const float*)d_in[8];
    const float* be1 = (const float*)d_in[9];
    const float* g2  = (const float*)d_in[10];
    const float* be2 = (const float*)d_in[11];
    const float* W1  = (const float*)d_in[12];
    const float* bb1 = (const float*)d_in[13];
    const float* W2  = (const float*)d_in[14];
    const float* bb2 = (const float*)d_in[15];
    const float* gf  = (const float*)d_in[16];
    const float* bf  = (const float*)d_in[17];
    const float* Wh  = (const float*)d_in[18];
    const float* bhd = (const float*)d_in[19];
    float* out = (float*)d_out;

    float    *x, *att;
    unsigned *qkv2;
    uint2    *h2, *o2, *a12, *wcat2, *wp2, *w12, *w22, *wh2;
    cudaGetSymbolAddress((void**)&x,     g_x);
    cudaGetSymbolAddress((void**)&h2,    g_h2);
    cudaGetSymbolAddress((void**)&qkv2,  g_qkv2);
    cudaGetSymbolAddress((void**)&o2,    g_o2);
    cudaGetSymbolAddress((void**)&a12,   g_a12);
    cudaGetSymbolAddress((void**)&att,   g_att);
    cudaGetSymbolAddress((void**)&wcat2, g_wcat2);
    cudaGetSymbolAddress((void**)&wp2,   g_wp2);
    cudaGetSymbolAddress((void**)&w12,   g_w12);
    cudaGetSymbolAddress((void**)&w22,   g_w22);
    cudaGetSymbolAddress((void**)&wh2,   g_wh2);

    const float att_scale = 0.03608439182435161f;  // 768^-0.5 (reference uses full C)
    const float* NOF = (const float*)0;

    embed_k<<<BT_, 256>>>(idx, tok, pos, x);

    // --- pre-split + pre-pack all weights (batched over layers) ---
    pack_qkv_pp<<<(L_ * (C_ / 2) * C_ + 255) / 256, 256>>>(Wq, Wk, Wv, wcat2);
    pack_w<<<(L_ * (C_ / 2) * C_  + 255) / 256, 256>>>(Wp, wp2, L_ * C_ / 2, C_);
    pack_w<<<(L_ * (C_ / 2) * C4_ + 255) / 256, 256>>>(W1, w12, L_ * C_ / 2, C4_);
    pack_w<<<(L_ * (C4_ / 2) * C_ + 255) / 256, 256>>>(W2, w22, L_ * C4_ / 2, C_);
    pack_w<<<((C_ / 2) * V_ + 255) / 256, 256>>>(Wh, wh2, C_ / 2, V_);

    dim3 gqkv(C3_ / 128, BT_ / 128, 1);
    dim3 gcc (C_  / 128, BT_ / 128, 1);
    dim3 gsc (T_  / 128, T_  / 128, B_ * H_);
    dim3 gav (1,         T_  / 128, B_ * H_);
    dim3 gf1 (C4_ / 128, BT_ / 128, 1);

    for (int l = 0; l < L_; l++) {
        layernorm_pp<<<BT_, 256>>>(x, g1 + l * C_, be1 + l * C_, h2);

        // qkv = h @ Wcat -> EW u32 [BT][3C]
        gemm_lin<<<gqkv, 512, SMEM_BYTES>>>(h2, wcat2 + (size_t)l * (C_/2) * C3_,
                (float*)qkv2, BT_, C3_, C_, NOF, NOF, 0, 1);

        // scores: Q @ K^T per (b,h) -> plain att, upper blocks skipped
        gemm_sc<<<gsc, 512, SMEM_BYTES>>>(qkv2, att, att_scale);

        softmax_causal<<<B_ * H_ * T_, 256>>>(att);

        // AV: P(PP) @ V -> o (PP), causally clamped K
        gemm_av<<<gav, 256, SMEM_BYTES>>>(att, qkv2, o2);

        // x = x + o @ Wproj + bproj (plain out)
        gemm_lin<<<gcc, 512, SMEM_BYTES>>>(o2, wp2 + (size_t)l * (C_/2) * C_,
                x, BT_, C_, C_, bp + l * C_, x, 0, 0);

        layernorm_pp<<<BT_, 256>>>(x, g2 + l * C_, be2 + l * C_, h2);

        // a1 = gelu(h @ W1 + b1) -> PP
        gemm_lin<<<gf1, 512, SMEM_BYTES>>>(h2, w12 + (size_t)l * (C_/2) * C4_,
                (float*)a12, BT_, C4_, C_, bb1 + l * C4_, NOF, 1, 2);

        // x = x + a1 @ W2 + b2 (plain out)
        gemm_lin<<<gcc, 512, SMEM_BYTES>>>(a12, w22 + (size_t)l * (C4_/2) * C_,
                x, BT_, C_, C4_, bb2 + l * C_, x, 0, 0);
    }

    layernorm_pp<<<BT_, 256>>>(x, gf, bf, h2);

    // head: 3-term bf16
    dim3 ghd(V_ / 128, BT_ / 128, 1);
    gemm_lin<<<ghd, 512, SMEM_BYTES>>>(h2, wh2, out, BT_, V_, C_, bhd, NOF, 0, 0);
}

// round 14
// speedup vs baseline: 2.2329x; 1.0147x over previous
#include <cuda_runtime.h>
#include <cuda_bf16.h>
#include <math.h>

// ---------------------------------------------------------------------------
// GPT-2 small forward. fp32 activations; GEMMs use split-bf16 (3xBF16)
// mma.sync.m16n8k16 on pre-split, pre-packed k-pair planar uint2 operands.
// Linear GEMMs: KT=32 double-buffered, 512-thr 128x128 tiles; a 256-thr
// 64x128 variant (2 CTAs/SM) fixes wave quantization for the 192-CTA
// proj/fc2 launches. Causal-aware attention.
// ---------------------------------------------------------------------------

namespace {
constexpr int B_  = 4;
constexpr int T_  = 1024;
constexpr int C_  = 768;
constexpr int H_  = 12;
constexpr int HS_ = 64;
constexpr int L_  = 12;
constexpr int V_  = 32000;
constexpr int BT_ = B_ * T_;
constexpr int C4_ = 4 * C_;
constexpr int C3_ = 3 * C_;

constexpr int P2  = 132;                // B smem row pitch in uint2

// attention kernels (KT=16)
constexpr int K2T   = 8;                // k-pairs per tile
constexpr int STG2  = 2 * K2T * P2;     // uint2 per stage
constexpr size_t SMEM_SA = 2 * STG2 * sizeof(uint2);      // 33792 B

// linear GEMM 128x128 (KT=32)
constexpr int K2L   = 16;
constexpr int STGL  = 2 * K2L * P2;     // 4224 uint2
constexpr size_t SMEM_LIN = 2 * STGL * sizeof(uint2);     // 67584 B

// linear GEMM 64x128 (KT=32), A-pitch 68
constexpr int PA64  = 68;
constexpr int STG64 = K2L * PA64 + K2L * P2;              // 3200 uint2
constexpr size_t SMEM_L64 = 2 * STG64 * sizeof(uint2);    // 51200 B
}

// Scratch (no cudaMalloc -> device globals)
__device__ float    g_x   [BT_ * C_];
__device__ uint2    g_h2  [BT_ * C_ / 2];      // PP: [row][C/2]
__device__ unsigned g_qkv2[BT_ * C3_];         // EW u32 per element
__device__ uint2    g_o2  [BT_ * C_ / 2];      // PP
__device__ uint2    g_a12 [BT_ * C4_ / 2];     // PP
__device__ float    g_att [(size_t)B_ * H_ * T_ * T_];
// all-layer pre-split packed weights: [k2][n] uint2
__device__ uint2 g_wcat2[(size_t)L_ * (C_ / 2) * C3_];
__device__ uint2 g_wp2  [(size_t)L_ * (C_ / 2) * C_];
__device__ uint2 g_w12  [(size_t)L_ * (C_ / 2) * C4_];
__device__ uint2 g_w22  [(size_t)L_ * (C4_ / 2) * C_];
__device__ uint2 g_wh2  [(size_t)(C_ / 2) * V_];

// ---------------------------------------------------------------------------
// bf16 split helpers
// ---------------------------------------------------------------------------
__device__ __forceinline__ unsigned splitbf(float x) {
    __nv_bfloat16 h = __float2bfloat16(x);
    float hf = __bfloat162float(h);
    __nv_bfloat16 l = __float2bfloat16(x - hf);
    return (unsigned)__bfloat16_as_ushort(h) |
           ((unsigned)__bfloat16_as_ushort(l) << 16);
}

#define HIPAIR(e0, e1) __byte_perm((e0), (e1), 0x5410)
#define LOPAIR(e0, e1) __byte_perm((e0), (e1), 0x7632)

__device__ __forceinline__ uint2 packpair(float a, float b) {
    unsigned u0 = splitbf(a), u1 = splitbf(b);
    return make_uint2(HIPAIR(u0, u1), LOPAIR(u0, u1));
}

__device__ __forceinline__ void mma_bf16(float* d, const unsigned* a,
                                         unsigned b0, unsigned b1) {
    asm volatile(
        "mma.sync.aligned.m16n8k16.row.col.f32.bf16.bf16.f32 "
        "{%0,%1,%2,%3}, {%4,%5,%6,%7}, {%8,%9}, {%0,%1,%2,%3};"
        : "+f"(d[0]), "+f"(d[1]), "+f"(d[2]), "+f"(d[3])
        : "r"(a[0]), "r"(a[1]), "r"(a[2]), "r"(a[3]),
          "r"(b0), "r"(b1));
}

// ---------------------------------------------------------------------------
// Linear GEMM 128x128, KT=32, 512 threads, 16 warps (4x4), warp tile 32x32.
// A: PP [M][K/2] uint2.  B: PP [K/2][N] uint2.
// outMode: 0 plain float, 1 EW u32, 2 PP uint2.  M%128, N%128, K%32 == 0.
// ---------------------------------------------------------------------------
__global__ void __launch_bounds__(512)
gemm_lin(const uint2* __restrict__ A, const uint2* __restrict__ Bw,
         float* __restrict__ Cp, int M, int N, int K,
         const float* __restrict__ bias, const float* __restrict__ resid,
         int doGelu, int outMode)
{
    extern __shared__ uint2 smbuf[];
    const int ldaH = K >> 1;

    int m0   = blockIdx.y << 7;
    int n0   = blockIdx.x << 7;
    int tid  = threadIdx.x;
    int lane = tid & 31;
    int wid  = tid >> 5;
    int wm   = (wid & 3) << 5;
    int wn   = (wid >> 2) << 5;

    float acc[2][4][4];
    #pragma unroll
    for (int a = 0; a < 2; a++)
        #pragma unroll
        for (int b = 0; b < 4; b++)
            #pragma unroll
            for (int j = 0; j < 4; j++) acc[a][b][j] = 0.f;

    const int la_m  = tid >> 2;             // 0..127
    const int la_k2 = (tid & 3) << 2;       // 0,4,8,12
    const int lb_k2 = tid >> 5;             // 0..15
    const int lb_n  = (tid & 31) << 2;      // 0..124

    uint4 ra[2], rb[2];
    const int nk = K >> 5;

    auto LOAD = [&](int kh) {   // kh = k-pair base of tile
        const uint4* pa = (const uint4*)(A + (size_t)(m0 + la_m) * ldaH + (kh + la_k2));
        ra[0] = pa[0]; ra[1] = pa[1];
        const uint4* pb = (const uint4*)(Bw + (size_t)(kh + lb_k2) * N + (n0 + lb_n));
        rb[0] = pb[0]; rb[1] = pb[1];
    };
    auto STORE = [&](int s) {
        uint2* As = smbuf + s * STGL;
        uint2* Bs = As + K2L * P2;
        As[(la_k2 + 0) * P2 + la_m] = make_uint2(ra[0].x, ra[0].y);
        As[(la_k2 + 1) * P2 + la_m] = make_uint2(ra[0].z, ra[0].w);
        As[(la_k2 + 2) * P2 + la_m] = make_uint2(ra[1].x, ra[1].y);
        As[(la_k2 + 3) * P2 + la_m] = make_uint2(ra[1].z, ra[1].w);
        *(uint4*)&Bs[lb_k2 * P2 + lb_n]     = rb[0];
        *(uint4*)&Bs[lb_k2 * P2 + lb_n + 2] = rb[1];
    };

    LOAD(0);
    STORE(0);
    __syncthreads();

    for (int t = 0; t < nk; t++) {
        if (t + 1 < nk) LOAD((t + 1) << 4);

        const uint2* As = smbuf + (t & 1) * STGL;
        const uint2* Bs = As + K2L * P2;

        #pragma unroll
        for (int kh = 0; kh < 2; kh++) {
            int k2q = (kh << 3) + (lane & 3);
            int qd  = lane >> 2;
            uint2 aA[2][4];
            #pragma unroll
            for (int mt = 0; mt < 2; mt++) {
                int r = wm + (mt << 4) + qd;
                aA[mt][0] = As[ k2q      * P2 + r];
                aA[mt][1] = As[ k2q      * P2 + r + 8];
                aA[mt][2] = As[(k2q + 4) * P2 + r];
                aA[mt][3] = As[(k2q + 4) * P2 + r + 8];
            }
            uint2 bB[4][2];
            #pragma unroll
            for (int nt = 0; nt < 4; nt++) {
                int cn = wn + (nt << 3) + qd;
                bB[nt][0] = Bs[ k2q      * P2 + cn];
                bB[nt][1] = Bs[(k2q + 4) * P2 + cn];
            }
            #pragma unroll
            for (int mt = 0; mt < 2; mt++) {
                unsigned ah[4] = {aA[mt][0].x, aA[mt][1].x, aA[mt][2].x, aA[mt][3].x};
                unsigned al[4] = {aA[mt][0].y, aA[mt][1].y, aA[mt][2].y, aA[mt][3].y};
                #pragma unroll
                for (int nt = 0; nt < 4; nt++) {
                    mma_bf16(acc[mt][nt], ah, bB[nt][0].x, bB[nt][1].x);
                    mma_bf16(acc[mt][nt], ah, bB[nt][0].y, bB[nt][1].y);
                    mma_bf16(acc[mt][nt], al, bB[nt][0].x, bB[nt][1].x);
                }
            }
        }

        if (t + 1 < nk) STORE((t + 1) & 1);
        __syncthreads();
    }

    // ---- epilogue ----
    unsigned* Cu = (unsigned*)Cp;
    uint2*    Cq = (uint2*)Cp;
    #pragma unroll
    for (int mt = 0; mt < 2; mt++) {
        #pragma unroll
        for (int nt = 0; nt < 4; nt++) {
            int row = m0 + wm + (mt << 4) + (lane >> 2);
            int col = n0 + wn + (nt << 3) + ((lane & 3) << 1);
            float v[4];
            #pragma unroll
            for (int j = 0; j < 4; j++) {
                int r = row + ((j & 2) ? 8 : 0);
                int c = col + (j & 1);
                float vv = acc[mt][nt][j];
                if (bias) vv += bias[c];
                if (doGelu) vv = 0.5f * vv * (1.f + erff(vv * 0.70710678118654752f));
                if (resid) vv += resid[(size_t)r * N + c];
                v[j] = vv;
            }
            if (outMode == 0) {
                *(float2*)&Cp[(size_t)row * N + col]       = make_float2(v[0], v[1]);
                *(float2*)&Cp[(size_t)(row + 8) * N + col] = make_float2(v[2], v[3]);
            } else if (outMode == 1) {
                Cu[(size_t)row * N + col]           = splitbf(v[0]);
                Cu[(size_t)row * N + col + 1]       = splitbf(v[1]);
                Cu[(size_t)(row + 8) * N + col]     = splitbf(v[2]);
                Cu[(size_t)(row + 8) * N + col + 1] = splitbf(v[3]);
            } else {
                Cq[(size_t)row * (N >> 1) + (col >> 1)]       = packpair(v[0], v[1]);
                Cq[(size_t)(row + 8) * (N >> 1) + (col >> 1)] = packpair(v[2], v[3]);
            }
        }
    }
}

// ---------------------------------------------------------------------------
// Linear GEMM 64x128, KT=32, 256 threads, 8 warps (2x4), warp tile 32x32.
// 2 CTAs/SM. Plain-float output with bias+resid (used for proj and fc2).
// ---------------------------------------------------------------------------
__global__ void __launch_bounds__(256, 2)
gemm_lin64(const uint2* __restrict__ A, const uint2* __restrict__ Bw,
           float* __restrict__ Cp, int N, int K,
           const float* __restrict__ bias, const float* __restrict__ resid)
{
    extern __shared__ uint2 smbuf[];
    const int ldaH = K >> 1;

    int m0   = blockIdx.y << 6;
    int n0   = blockIdx.x << 7;
    int tid  = threadIdx.x;
    int lane = tid & 31;
    int wid  = tid >> 5;
    int wm   = (wid & 1) << 5;      // 0,32
    int wn   = (wid >> 1) << 5;     // 0,32,64,96

    float acc[2][4][4];
    #pragma unroll
    for (int a = 0; a < 2; a++)
        #pragma unroll
        for (int b = 0; b < 4; b++)
            #pragma unroll
            for (int j = 0; j < 4; j++) acc[a][b][j] = 0.f;

    const int la_m  = tid >> 2;             // 0..63
    const int la_k2 = (tid & 3) << 2;       // 0,4,8,12
    const int lb_k2 = tid >> 4;             // 0..15
    const int lb_n  = (tid & 15) << 3;      // 0..120

    uint4 ra[2], rb[4];
    const int nk = K >> 5;

    auto LOAD = [&](int kh) {
        const uint4* pa = (const uint4*)(A + (size_t)(m0 + la_m) * ldaH + (kh + la_k2));
        ra[0] = pa[0]; ra[1] = pa[1];
        const uint4* pb = (const uint4*)(Bw + (size_t)(kh + lb_k2) * N + (n0 + lb_n));
        rb[0] = pb[0]; rb[1] = pb[1]; rb[2] = pb[2]; rb[3] = pb[3];
    };
    auto STORE = [&](int s) {
        uint2* As = smbuf + s * STG64;
        uint2* Bs = As + K2L * PA64;
        As[(la_k2 + 0) * PA64 + la_m] = make_uint2(ra[0].x, ra[0].y);
        As[(la_k2 + 1) * PA64 + la_m] = make_uint2(ra[0].z, ra[0].w);
        As[(la_k2 + 2) * PA64 + la_m] = make_uint2(ra[1].x, ra[1].y);
        As[(la_k2 + 3) * PA64 + la_m] = make_uint2(ra[1].z, ra[1].w);
        uint4* bp4 = (uint4*)&Bs[lb_k2 * P2 + lb_n];
        bp4[0] = rb[0]; bp4[1] = rb[1]; bp4[2] = rb[2]; bp4[3] = rb[3];
    };

    LOAD(0);
    STORE(0);
    __syncthreads();

    for (int t = 0; t < nk; t++) {
        if (t + 1 < nk) LOAD((t + 1) << 4);

        const uint2* As = smbuf + (t & 1) * STG64;
        const uint2* Bs = As + K2L * PA64;

        #pragma unroll
        for (int kh = 0; kh < 2; kh++) {
            int k2q = (kh << 3) + (lane & 3);
            int qd  = lane >> 2;
            uint2 aA[2][4];
            #pragma unroll
            for (int mt = 0; mt < 2; mt++) {
                int r = wm + (mt << 4) + qd;
                aA[mt][0] = As[ k2q      * PA64 + r];
                aA[mt][1] = As[ k2q      * PA64 + r + 8];
                aA[mt][2] = As[(k2q + 4) * PA64 + r];
                aA[mt][3] = As[(k2q + 4) * PA64 + r + 8];
            }
            uint2 bB[4][2];
            #pragma unroll
            for (int nt = 0; nt < 4; nt++) {
                int cn = wn + (nt << 3) + qd;
                bB[nt][0] = Bs[ k2q      * P2 + cn];
                bB[nt][1] = Bs[(k2q + 4) * P2 + cn];
            }
            #pragma unroll
            for (int mt = 0; mt < 2; mt++) {
                unsigned ah[4] = {aA[mt][0].x, aA[mt][1].x, aA[mt][2].x, aA[mt][3].x};
                unsigned al[4] = {aA[mt][0].y, aA[mt][1].y, aA[mt][2].y, aA[mt][3].y};
                #pragma unroll
                for (int nt = 0; nt < 4; nt++) {
                    mma_bf16(acc[mt][nt], ah, bB[nt][0].x, bB[nt][1].x);
                    mma_bf16(acc[mt][nt], ah, bB[nt][0].y, bB[nt][1].y);
                    mma_bf16(acc[mt][nt], al, bB[nt][0].x, bB[nt][1].x);
                }
            }
        }

        if (t + 1 < nk) STORE((t + 1) & 1);
        __syncthreads();
    }

    #pragma unroll
    for (int mt = 0; mt < 2; mt++) {
        #pragma unroll
        for (int nt = 0; nt < 4; nt++) {
            int row = m0 + wm + (mt << 4) + (lane >> 2);
            int col = n0 + wn + (nt << 3) + ((lane & 3) << 1);
            float v[4];
            #pragma unroll
            for (int j = 0; j < 4; j++) {
                int r = row + ((j & 2) ? 8 : 0);
                int c = col + (j & 1);
                v[j] = acc[mt][nt][j] + bias[c] + resid[(size_t)r * N + c];
            }
            *(float2*)&Cp[(size_t)row * N + col]       = make_float2(v[0], v[1]);
            *(float2*)&Cp[(size_t)(row + 8) * N + col] = make_float2(v[2], v[3]);
        }
    }
}

// ---------------------------------------------------------------------------
// Scores GEMM: att[b,h] = Q @ K^T * alpha. EW u32 operands in qkv2.
// 512 threads, tile 128x128, K=HS=64 (KT=16). Upper blocks skipped.
// ---------------------------------------------------------------------------
__global__ void __launch_bounds__(512)
gemm_sc(const unsigned* __restrict__ qkv, float* __restrict__ att, float alpha)
{
    if (blockIdx.x > blockIdx.y) return;
    extern __shared__ uint2 smbuf[];

    int bz = blockIdx.z;
    const unsigned* A  = qkv + (size_t)(bz / H_) * T_ * C3_ + (size_t)(bz % H_) * HS_;
    const unsigned* Bq = A + C_;
    float* Cb = att + (size_t)bz * T_ * T_;

    int m0   = blockIdx.y << 7;
    int n0   = blockIdx.x << 7;
    int tid  = threadIdx.x;
    int lane = tid & 31;
    int wid  = tid >> 5;
    int wm   = (wid & 3) << 5;
    int wn   = (wid >> 2) << 5;

    float acc[2][4][4];
    #pragma unroll
    for (int a = 0; a < 2; a++)
        #pragma unroll
        for (int b = 0; b < 4; b++)
            #pragma unroll
            for (int j = 0; j < 4; j++) acc[a][b][j] = 0.f;

    const int la_m = tid >> 2;
    const int la_k = (tid & 3) << 2;

    uint4 ra, rbT;
    const int nk = HS_ >> 4;

    auto LOAD = [&](int k0) {
        ra  = *(const uint4*)(A  + (size_t)(m0 + la_m) * C3_ + (k0 + la_k));
        rbT = *(const uint4*)(Bq + (size_t)(n0 + la_m) * C3_ + (k0 + la_k));
    };
    auto STORE = [&](int s) {
        uint2* As = smbuf + s * STG2;
        uint2* Bs = As + K2T * P2;
        int k2 = la_k >> 1;
        As[(k2    ) * P2 + la_m] = make_uint2(HIPAIR(ra.x, ra.y), LOPAIR(ra.x, ra.y));
        As[(k2 + 1) * P2 + la_m] = make_uint2(HIPAIR(ra.z, ra.w), LOPAIR(ra.z, ra.w));
        Bs[(k2    ) * P2 + la_m] = make_uint2(HIPAIR(rbT.x, rbT.y), LOPAIR(rbT.x, rbT.y));
        Bs[(k2 + 1) * P2 + la_m] = make_uint2(HIPAIR(rbT.z, rbT.w), LOPAIR(rbT.z, rbT.w));
    };

    LOAD(0);
    STORE(0);
    __syncthreads();

    for (int t = 0; t < nk; t++) {
        if (t + 1 < nk) LOAD((t + 1) << 4);

        const uint2* As = smbuf + (t & 1) * STG2;
        const uint2* Bs = As + K2T * P2;

        int k2q = lane & 3;
        int qd  = lane >> 2;
        uint2 aA[2][4];
        #pragma unroll
        for (int mt = 0; mt < 2; mt++) {
            int r = wm + (mt << 4) + qd;
            aA[mt][0] = As[ k2q      * P2 + r];
            aA[mt][1] = As[ k2q      * P2 + r + 8];
            aA[mt][2] = As[(k2q + 4) * P2 + r];
            aA[mt][3] = As[(k2q + 4) * P2 + r + 8];
        }
        uint2 bB[4][2];
        #pragma unroll
        for (int nt = 0; nt < 4; nt++) {
            int cn = wn + (nt << 3) + qd;
            bB[nt][0] = Bs[ k2q      * P2 + cn];
            bB[nt][1] = Bs[(k2q + 4) * P2 + cn];
        }
        #pragma unroll
        for (int mt = 0; mt < 2; mt++) {
            unsigned ah[4] = {aA[mt][0].x, aA[mt][1].x, aA[mt][2].x, aA[mt][3].x};
            unsigned al[4] = {aA[mt][0].y, aA[mt][1].y, aA[mt][2].y, aA[mt][3].y};
            #pragma unroll
            for (int nt = 0; nt < 4; nt++) {
                mma_bf16(acc[mt][nt], ah, bB[nt][0].x, bB[nt][1].x);
                mma_bf16(acc[mt][nt], ah, bB[nt][0].y, bB[nt][1].y);
                mma_bf16(acc[mt][nt], al, bB[nt][0].x, bB[nt][1].x);
            }
        }

        if (t + 1 < nk) STORE((t + 1) & 1);
        __syncthreads();
    }

    #pragma unroll
    for (int mt = 0; mt < 2; mt++) {
        #pragma unroll
        for (int nt = 0; nt < 4; nt++) {
            int row = m0 + wm + (mt << 4) + (lane >> 2);
            int col = n0 + wn + (nt << 3) + ((lane & 3) << 1);
            *(float2*)&Cb[(size_t)row * T_ + col] =
                make_float2(acc[mt][nt][0] * alpha, acc[mt][nt][1] * alpha);
            *(float2*)&Cb[(size_t)(row + 8) * T_ + col] =
                make_float2(acc[mt][nt][2] * alpha, acc[mt][nt][3] * alpha);
        }
    }
}

// ---------------------------------------------------------------------------
// AV GEMM: o[b,h] = P @ V. A = att (PP in place by softmax). B = V (EW u32,
// PRMT-packed in staging). 256 threads, 8 warps x 1, warp tile 16x64.
// K causally clamped. Out PP. KT=16.
// ---------------------------------------------------------------------------
__global__ void __launch_bounds__(256)
gemm_av(const float* __restrict__ attf, const unsigned* __restrict__ qkv,
        uint2* __restrict__ o2)
{
    extern __shared__ uint2 smbuf[];
    int bz = blockIdx.z;
    const uint2* Apk = (const uint2*)attf + (size_t)bz * T_ * (T_ / 2);
    const unsigned* Bp = qkv + (size_t)(bz / H_) * T_ * C3_ + (size_t)(bz % H_) * HS_ + 2 * C_;
    uint2* Cq = o2 + (size_t)(bz / H_) * T_ * (C_ / 2) + (size_t)(bz % H_) * (HS_ / 2);

    int m0   = blockIdx.y << 7;
    int tid  = threadIdx.x;
    int lane = tid & 31;
    int wid  = tid >> 5;
    int wm   = wid << 4;

    const int nk = (m0 + 128) >> 4;     // causal clamp

    float acc[8][4];
    #pragma unroll
    for (int b = 0; b < 8; b++)
        #pragma unroll
        for (int j = 0; j < 4; j++) acc[b][j] = 0.f;

    const int la_m  = tid >> 2;
    const int la_k2 = (tid & 3) << 1;
    const int lb_k2 = tid >> 5;
    const int lb_n  = (tid & 31) << 1;

    uint4 ra[2]; uint2 rb0, rb1;

    auto LOAD = [&](int kh) {
        #pragma unroll
        for (int j = 0; j < 2; j++) {
            int m = la_m + (j << 6);
            ra[j] = *(const uint4*)(Apk + (size_t)(m0 + m) * (T_ / 2) + (kh + la_k2));
        }
        int k0 = kh << 1;
        rb0 = *(const uint2*)(Bp + (size_t)(k0 + 2 * lb_k2)     * C3_ + lb_n);
        rb1 = *(const uint2*)(Bp + (size_t)(k0 + 2 * lb_k2 + 1) * C3_ + lb_n);
    };
    auto STORE = [&](int s) {
        uint2* As = smbuf + s * STG2;
        uint2* Bs = As + K2T * P2;
        #pragma unroll
        for (int j = 0; j < 2; j++) {
            int m = la_m + (j << 6);
            As[(la_k2    ) * P2 + m] = make_uint2(ra[j].x, ra[j].y);
            As[(la_k2 + 1) * P2 + m] = make_uint2(ra[j].z, ra[j].w);
        }
        Bs[lb_k2 * P2 + lb_n    ] = make_uint2(HIPAIR(rb0.x, rb1.x), LOPAIR(rb0.x, rb1.x));
        Bs[lb_k2 * P2 + lb_n + 1] = make_uint2(HIPAIR(rb0.y, rb1.y), LOPAIR(rb0.y, rb1.y));
    };

    LOAD(0);
    STORE(0);
    __syncthreads();

    for (int t = 0; t < nk; t++) {
        if (t + 1 < nk) LOAD((t + 1) << 3);

        const uint2* As = smbuf + (t & 1) * STG2;
        const uint2* Bs = As + K2T * P2;

        int k2q = lane & 3;
        int qd  = lane >> 2;
        int r   = wm + qd;
        uint2 a0 = As[ k2q      * P2 + r];
        uint2 a1 = As[ k2q      * P2 + r + 8];
        uint2 a2 = As[(k2q + 4) * P2 + r];
        uint2 a3 = As[(k2q + 4) * P2 + r + 8];
        unsigned ah[4] = {a0.x, a1.x, a2.x, a3.x};
        unsigned al[4] = {a0.y, a1.y, a2.y, a3.y};
        #pragma unroll
        for (int nt = 0; nt < 8; nt++) {
            int cn = (nt << 3) + qd;
            uint2 b0 = Bs[ k2q      * P2 + cn];
            uint2 b1 = Bs[(k2q + 4) * P2 + cn];
            mma_bf16(acc[nt], ah, b0.x, b1.x);
            mma_bf16(acc[nt], ah, b0.y, b1.y);
            mma_bf16(acc[nt], al, b0.x, b1.x);
        }

        if (t + 1 < nk) STORE((t + 1) & 1);
        __syncthreads();
    }

    #pragma unroll
    for (int nt = 0; nt < 8; nt++) {
        int row = m0 + wm + (lane >> 2);
        int col = (nt << 3) + ((lane & 3) << 1);
        Cq[(size_t)row * (C_ / 2) + (col >> 1)]       = packpair(acc[nt][0], acc[nt][1]);
        Cq[(size_t)(row + 8) * (C_ / 2) + (col >> 1)] = packpair(acc[nt][2], acc[nt][3]);
    }
}

// ---------------------------------------------------------------------------
// Weight pre-pack: src rows paired -> PP [rows/2][N] uint2
// ---------------------------------------------------------------------------
__global__ void pack_w(const float* __restrict__ src, uint2* __restrict__ dst,
                       int halfRows, int N)
{
    int i = blockIdx.x * 256 + threadIdx.x;
    if (i < halfRows * N) {
        int g = i / N, j = i - g * N;
        dst[i] = packpair(src[(size_t)(2 * g) * N + j],
                          src[(size_t)(2 * g + 1) * N + j]);
    }
}

// Pack Wq/Wk/Wv [L][C][C] -> PP Wcat [L][C/2][3C]
__global__ void pack_qkv_pp(const float* __restrict__ Wq, const float* __restrict__ Wk,
                            const float* __restrict__ Wv, uint2* __restrict__ Wcat)
{
    int i = blockIdx.x * 256 + threadIdx.x;
    if (i < L_ * (C_ / 2) * C_) {
        int l  = i / ((C_ / 2) * C_);
        int rm = i - l * ((C_ / 2) * C_);
        int k2 = rm / C_, j = rm - k2 * C_;
        size_t so = (size_t)l * C_ * C_;
        uint2* W = Wcat + (size_t)l * (C_ / 2) * C3_ + (size_t)k2 * C3_;
        W[j]            = packpair(Wq[so + (size_t)(2*k2) * C_ + j], Wq[so + (size_t)(2*k2+1) * C_ + j]);
        W[C_ + j]       = packpair(Wk[so + (size_t)(2*k2) * C_ + j], Wk[so + (size_t)(2*k2+1) * C_ + j]);
        W[2 * C_ + j]   = packpair(Wv[so + (size_t)(2*k2) * C_ + j], Wv[so + (size_t)(2*k2+1) * C_ + j]);
    }
}

// ---------------------------------------------------------------------------
// LayerNorm (biased variance, eps=1e-5) -> PP uint2 output
// ---------------------------------------------------------------------------
__global__ void layernorm_pp(const float* __restrict__ x, const float* __restrict__ g,
                             const float* __restrict__ b, uint2* __restrict__ y)
{
    int row = blockIdx.x;
    const float* xr = x + (size_t)row * C_;
    uint2* yr       = y + (size_t)row * (C_ / 2);
    int tid = threadIdx.x;
    float s = 0.f, s2 = 0.f;
    for (int c = tid; c < C_; c += 256) { float v = xr[c]; s += v; s2 += v * v; }
    __shared__ float shs[8], shs2[8];
    #pragma unroll
    for (int o = 16; o; o >>= 1) {
        s  += __shfl_xor_sync(0xffffffffu, s,  o);
        s2 += __shfl_xor_sync(0xffffffffu, s2, o);
    }
    if ((tid & 31) == 0) { shs[tid >> 5] = s; shs2[tid >> 5] = s2; }
    __syncthreads();
    float ts = 0.f, ts2 = 0.f;
    #pragma unroll
    for (int i = 0; i < 8; i++) { ts += shs[i]; ts2 += shs2[i]; }
    float mean = ts * (1.f / C_);
    float var  = ts2 * (1.f / C_) - mean * mean;
    float rstd = rsqrtf(var + 1e-5f);
    for (int p = tid; p < C_ / 2; p += 256) {
        float2 xv = ((const float2*)xr)[p];
        float2 gv = ((const float2*)g)[p];
        float2 bv = ((const float2*)b)[p];
        yr[p] = packpair((xv.x - mean) * rstd * gv.x + bv.x,
                         (xv.y - mean) * rstd * gv.y + bv.y);
    }
}

// ---------------------------------------------------------------------------
// Causal softmax: read plain float att row, write SPLIT-PACKED uint2 pairs
// in place. Writes only to the next 128 boundary.
// ---------------------------------------------------------------------------
__global__ void softmax_causal(float* __restrict__ att)
{
    int row = blockIdx.x;             // b*H*T + h*T + q
    int q   = row & (T_ - 1);
    float* a = att + (size_t)row * T_;
    uint2* apk = (uint2*)a;
    int len  = q + 1;
    int wlim = ((q >> 7) + 1) << 7;
    int tid  = threadIdx.x;
    __shared__ float sh[8];

    float r[4];
    #pragma unroll
    for (int i = 0; i < 2; i++) {
        int p = tid + (i << 8);
        float2 v = ((const float2*)a)[p];
        r[2*i]     = (2*p     < len) ? v.x : -3.0e38f;
        r[2*i + 1] = (2*p + 1 < len) ? v.y : -3.0e38f;
    }
    float mx = fmaxf(fmaxf(r[0], r[1]), fmaxf(r[2], r[3]));
    #pragma unroll
    for (int o = 16; o; o >>= 1) mx = fmaxf(mx, __shfl_xor_sync(0xffffffffu, mx, o));
    if ((tid & 31) == 0) sh[tid >> 5] = mx;
    __syncthreads();
    mx = sh[0];
    #pragma unroll
    for (int i = 1; i < 8; i++) mx = fmaxf(mx, sh[i]);
    __syncthreads();

    float s = 0.f;
    #pragma unroll
    for (int i = 0; i < 2; i++) {
        int p = tid + (i << 8);
        r[2*i]     = (2*p     < len) ? expf(r[2*i]     - mx) : 0.f;
        r[2*i + 1] = (2*p + 1 < len) ? expf(r[2*i + 1] - mx) : 0.f;
        s += r[2*i] + r[2*i + 1];
    }
    #pragma unroll
    for (int o = 16; o; o >>= 1) s += __shfl_xor_sync(0xffffffffu, s, o);
    if ((tid & 31) == 0) sh[tid >> 5] = s;
    __syncthreads();
    float tot = 0.f;
    #pragma unroll
    for (int i = 0; i < 8; i++) tot += sh[i];
    float inv = 1.f / tot;

    #pragma unroll
    for (int i = 0; i < 2; i++) {
        int p = tid + (i << 8);
        if (2 * p < wlim)
            apk[p] = packpair(r[2*i] * inv, r[2*i + 1] * inv);
    }
}

// ---------------------------------------------------------------------------
// Embedding
// ---------------------------------------------------------------------------
__global__ void embed_k(const int* __restrict__ idx, const float* __restrict__ tok,
                        const float* __restrict__ pos, float* __restrict__ x)
{
    int r = blockIdx.x;
    int t = r & (T_ - 1);
    int token = idx[r];
    const float* te = tok + (size_t)token * C_;
    const float* pe = pos + (size_t)t * C_;
    float* xr = x + (size_t)r * C_;
    for (int c = threadIdx.x; c < C_; c += 256) xr[c] = te[c] + pe[c];
}

// ---------------------------------------------------------------------------
// Launch
// ---------------------------------------------------------------------------
extern "C" void kernel_launch(void* const* d_in, const int* in_sizes, int n_in,
                              void* d_out, int out_size)
{
    (void)in_sizes; (void)n_in; (void)out_size;
    const int*   idx = (const int*)d_in[0];
    const float* tok = (const float*)d_in[1];
    const float* pos = (const float*)d_in[2];
    const float* Wq  = (const float*)d_in[3];
    const float* Wk  = (const float*)d_in[4];
    const float* Wv  = (const float*)d_in[5];
    const float* Wp  = (const float*)d_in[6];
    const float* bp  = (const float*)d_in[7];
    const float* g1  = (const float*)d_in[8];
    const float* be1 = (const float*)d_in[9];
    const float* g2  = (const float*)d_in[10];
    const float* be2 = (const float*)d_in[11];
    const float* W1  = (const float*)d_in[12];
    const float* bb1 = (const float*)d_in[13];
    const float* W2  = (const float*)d_in[14];
    const float* bb2 = (const float*)d_in[15];
    const float* gf  = (const float*)d_in[16];
    const float* bf  = (const float*)d_in[17];
    const float* Wh  = (const float*)d_in[18];
    const float* bhd = (const float*)d_in[19];
    float* out = (float*)d_out;

    float    *x, *att;
    unsigned *qkv2;
    uint2    *h2, *o2, *a12, *wcat2, *wp2, *w12, *w22, *wh2;
    cudaGetSymbolAddress((void**)&x,     g_x);
    cudaGetSymbolAddress((void**)&h2,    g_h2);
    cudaGetSymbolAddress((void**)&qkv2,  g_qkv2);
    cudaGetSymbolAddress((void**)&o2,    g_o2);
    cudaGetSymbolAddress((void**)&a12,   g_a12);
    cudaGetSymbolAddress((void**)&att,   g_att);
    cudaGetSymbolAddress((void**)&wcat2, g_wcat2);
    cudaGetSymbolAddress((void**)&wp2,   g_wp2);
    cudaGetSymbolAddress((void**)&w12,   g_w12);
    cudaGetSymbolAddress((void**)&w22,   g_w22);
    cudaGetSymbolAddress((void**)&wh2,   g_wh2);

    cudaFuncSetAttribute((const void*)gemm_lin,
                         cudaFuncAttributeMaxDynamicSharedMemorySize, (int)SMEM_LIN);
    cudaFuncSetAttribute((const void*)gemm_lin64,
                         cudaFuncAttributeMaxDynamicSharedMemorySize, (int)SMEM_L64);

    const float att_scale = 0.03608439182435161f;  // 768^-0.5 (reference uses full C)
    const float* NOF = (const float*)0;

    embed_k<<<BT_, 256>>>(idx, tok, pos, x);

    // --- pre-split + pre-pack all weights (batched over layers) ---
    pack_qkv_pp<<<(L_ * (C_ / 2) * C_ + 255) / 256, 256>>>(Wq, Wk, Wv, wcat2);
    pack_w<<<(L_ * (C_ / 2) * C_  + 255) / 256, 256>>>(Wp, wp2, L_ * C_ / 2, C_);
    pack_w<<<(L_ * (C_ / 2) * C4_ + 255) / 256, 256>>>(W1, w12, L_ * C_ / 2, C4_);
    pack_w<<<(L_ * (C4_ / 2) * C_ + 255) / 256, 256>>>(W2, w22, L_ * C4_ / 2, C_);
    pack_w<<<((C_ / 2) * V_ + 255) / 256, 256>>>(Wh, wh2, C_ / 2, V_);

    dim3 gqkv(C3_ / 128, BT_ / 128, 1);
    dim3 gc64(C_  / 128, BT_ / 64,  1);     // 6 x 64 = 384 CTAs
    dim3 gsc (T_  / 128, T_  / 128, B_ * H_);
    dim3 gav (1,         T_  / 128, B_ * H_);
    dim3 gf1 (C4_ / 128, BT_ / 128, 1);

    for (int l = 0; l < L_; l++) {
        layernorm_pp<<<BT_, 256>>>(x, g1 + l * C_, be1 + l * C_, h2);

        // qkv = h @ Wcat -> EW u32 [BT][3C]
        gemm_lin<<<gqkv, 512, SMEM_LIN>>>(h2, wcat2 + (size_t)l * (C_/2) * C3_,
                (float*)qkv2, BT_, C3_, C_, NOF, NOF, 0, 1);

        // scores: Q @ K^T per (b,h) -> plain att, upper blocks skipped
        gemm_sc<<<gsc, 512, SMEM_SA>>>(qkv2, att, att_scale);

        softmax_causal<<<B_ * H_ * T_, 256>>>(att);

        // AV: P(PP) @ V -> o (PP), causally clamped K
        gemm_av<<<gav, 256, SMEM_SA>>>(att, qkv2, o2);

        // x = x + o @ Wproj + bproj  (64-row tiles, 384 CTAs)
        gemm_lin64<<<gc64, 256, SMEM_L64>>>(o2, wp2 + (size_t)l * (C_/2) * C_,
                x, C_, C_, bp + l * C_, x);

        layernorm_pp<<<BT_, 256>>>(x, g2 + l * C_, be2 + l * C_, h2);

        // a1 = gelu(h @ W1 + b1) -> PP
        gemm_lin<<<gf1, 512, SMEM_LIN>>>(h2, w12 + (size_t)l * (C_/2) * C4_,
                (float*)a12, BT_, C4_, C_, bb1 + l * C4_, NOF, 1, 2);

        // x = x + a1 @ W2 + b2  (64-row tiles, 384 CTAs)
        gemm_lin64<<<gc64, 256, SMEM_L64>>>(a12, w22 + (size_t)l * (C4_/2) * C_,
                x, C_, C4_, bb2 + l * C_, x);
    }

    layernorm_pp<<<BT_, 256>>>(x, gf, bf, h2);

    // head: 3-term bf16
    dim3 ghd(V_ / 128, BT_ / 128, 1);
    gemm_lin<<<ghd, 512, SMEM_LIN>>>(h2, wh2, out, BT_, V_, C_, bhd, NOF, 0, 0);
}